// round 1
// baseline (speedup 1.0000x reference)
#include <cuda_runtime.h>
#include <cuda_bf16.h>
#include <math.h>

// ---------------- problem constants ----------------
#define BB   32
#define HH   56
#define WW   56
#define CC   256
#define WS   7
#define NH   8
#define HD   32
#define KCH  16
#define KSPT 28
#define NT   49          // tokens per window
#define MLPH 1024
#define LL   (HH*WW)     // 3136
#define ROWS (BB*LL)     // 100352
#define BW   2048        // windows
#define BN   (BW*NH)     // 16384
#define SCALE_F 0.17677669529663687f   // 32^-0.5

// ---------------- static scratch (no allocations allowed) ----------------
__device__ float g_xw[ROWS*CC];          // windowed LN1 output; later reused as proj output
__device__ float g_q[ROWS*CC];           // q; later reused as xn2 (LN2 output)
__device__ float g_obuf[ROWS*CC];        // attention output (window layout)
__device__ float g_qcha1[BW*NT*(CC/2)];  // channel-gathered q, (Bw,49,128)
__device__ float g_k[BW*NT*(CC/2)];      // k, (Bw,49,128)
__device__ float g_vbuf[BW*KSPT*CC];     // gathered v input, (Bw,28,256)
__device__ float g_vproj[BW*KSPT*CC];    // v after projection
__device__ float g_h[ROWS*MLPH];         // MLP hidden (411MB)
__device__ int   g_sidx[BN*KSPT];

// ---------------- helpers ----------------
__device__ __forceinline__ float gelu_exact(float x) {
    return 0.5f * x * (1.0f + erff(x * 0.70710678118654752f));
}

__device__ __forceinline__ float blockReduceSum256(float val) {
    __shared__ float sh[8];
    int lane = threadIdx.x & 31, wid = threadIdx.x >> 5;
    #pragma unroll
    for (int o = 16; o > 0; o >>= 1) val += __shfl_xor_sync(0xffffffffu, val, o);
    if (lane == 0) sh[wid] = val;
    __syncthreads();
    float r;
    if (wid == 0) {
        float v = (lane < 8) ? sh[lane] : 0.0f;
        #pragma unroll
        for (int o = 4; o > 0; o >>= 1) v += __shfl_xor_sync(0xffffffffu, v, o);
        if (lane == 0) sh[0] = v;
    }
    __syncthreads();
    r = sh[0];
    __syncthreads();
    return r;
}

// ---------------- LN1 + window partition ----------------
__global__ void ln1_window_kernel(const float* __restrict__ x,
                                  const float* __restrict__ g,
                                  const float* __restrict__ b) {
    int row = blockIdx.x, tid = threadIdx.x;
    float v = x[(size_t)row*CC + tid];
    float s1 = blockReduceSum256(v);
    float s2 = blockReduceSum256(v*v);
    float mu = s1 * (1.0f/CC);
    float var = s2 * (1.0f/CC) - mu*mu;
    float rstd = rsqrtf(var + 1e-5f);
    float o = (v - mu) * rstd * g[tid] + b[tid];
    int bidx = row / LL, l = row % LL;
    int h = l / WW, w = l % WW;
    int widx = (bidx*8 + h/WS)*8 + (w/WS);
    int token = (h%WS)*WS + (w%WS);
    g_xw[((size_t)widx*NT + token)*CC + tid] = o;
}

// ---------------- LN2 (plain) ----------------
__global__ void ln2_kernel(const float* __restrict__ x,
                           const float* __restrict__ g,
                           const float* __restrict__ b) {
    int row = blockIdx.x, tid = threadIdx.x;
    float v = x[(size_t)row*CC + tid];
    float s1 = blockReduceSum256(v);
    float s2 = blockReduceSum256(v*v);
    float mu = s1 * (1.0f/CC);
    float var = s2 * (1.0f/CC) - mu*mu;
    float rstd = rsqrtf(var + 1e-5f);
    g_q[(size_t)row*CC + tid] = (v - mu) * rstd * g[tid] + b[tid];
}

// ---------------- generic tiled SGEMM: D = act(A@W + bias) [+ res] ----------------
// A: MxK row-major, W: KxN row-major. BM=BN=64, BK=16, 256 threads, 4x4 per thread.
// Requires M%64==0, N%64==0, K%16==0 (true for all calls here).
template<int ACT>  // 0 = none, 1 = gelu
__global__ void sgemm_kernel(const float* __restrict__ A, const float* __restrict__ Wm,
                             const float* __restrict__ bias, const float* __restrict__ res,
                             float* __restrict__ D, int M, int K, int Ncols) {
    __shared__ float As[16][64];
    __shared__ float Bs[16][64];
    int tid = threadIdx.x;
    int tx = tid & 15, ty = tid >> 4;
    int bm = blockIdx.y * 64, bn = blockIdx.x * 64;
    float acc[4][4] = {};
    for (int k0 = 0; k0 < K; k0 += 16) {
        #pragma unroll
        for (int u = 0; u < 4; u++) {
            int lin = tid*4 + u;             // 0..1023
            int m = lin >> 4, kk = lin & 15; // A tile 64x16
            As[kk][m] = A[(size_t)(bm+m)*K + k0 + kk];
        }
        #pragma unroll
        for (int u = 0; u < 4; u++) {
            int lin = tid*4 + u;
            int kk = lin >> 6, n = lin & 63; // B tile 16x64
            Bs[kk][n] = Wm[(size_t)(k0+kk)*Ncols + bn + n];
        }
        __syncthreads();
        #pragma unroll
        for (int kk = 0; kk < 16; kk++) {
            float ra[4], rb[4];
            #pragma unroll
            for (int i = 0; i < 4; i++) ra[i] = As[kk][ty*4+i];
            #pragma unroll
            for (int j = 0; j < 4; j++) rb[j] = Bs[kk][tx*4+j];
            #pragma unroll
            for (int i = 0; i < 4; i++)
                #pragma unroll
                for (int j = 0; j < 4; j++) acc[i][j] += ra[i]*rb[j];
        }
        __syncthreads();
    }
    #pragma unroll
    for (int i = 0; i < 4; i++) {
        int row = bm + ty*4 + i;
        #pragma unroll
        for (int j = 0; j < 4; j++) {
            int col = bn + tx*4 + j;
            float v = acc[i][j] + bias[col];
            if (ACT == 1) v = gelu_exact(v);
            size_t idx = (size_t)row*Ncols + col;
            if (res) v += res[idx];
            D[idx] = v;
        }
    }
}

// ---------------- per-(window,head): stats, channel/spatial top-k, gathers ----------------
__global__ void topk_stats_kernel(const float* __restrict__ wch,
                                  const float* __restrict__ bch) {
    int bn = blockIdx.x;
    int widx = bn >> 3, nh = bn & 7;
    __shared__ float qt[NT*HD];
    __shared__ float cmean[HD], cmax[HD], tmean[NT], score[HD];
    __shared__ int cidx[KCH], sidx[KSPT];
    int tid = threadIdx.x;
    const float* qbase = g_q + (size_t)widx*NT*CC + nh*HD;
    for (int i = tid; i < NT*HD; i += 256) {
        int t = i >> 5, hd = i & 31;
        qt[i] = qbase[(size_t)t*CC + hd];
    }
    __syncthreads();
    if (tid < HD) {
        float s = 0.0f, m = -1e30f;
        for (int t = 0; t < NT; t++) { float v = qt[t*HD + tid]; s += v; m = fmaxf(m, v); }
        cmean[tid] = s * (1.0f/NT); cmax[tid] = m;
    }
    if (tid >= 64 && tid < 64 + NT) {
        int t = tid - 64;
        float s = 0.0f;
        for (int hd = 0; hd < HD; hd++) s += qt[t*HD + hd];
        tmean[t] = s * (1.0f/HD);
    }
    __syncthreads();
    if (tid < HD) {
        float s = bch[tid];
        for (int i = 0; i < HD; i++) s += cmean[i] * wch[i*HD + tid];
        for (int i = 0; i < HD; i++) s += cmax[i]  * wch[(HD+i)*HD + tid];
        score[tid] = gelu_exact(s);   // softmax before top_k is monotonic -> skip
    }
    __syncthreads();
    if (tid == 0) {
        float sc[HD];
        int sel[KCH];
        for (int i = 0; i < HD; i++) sc[i] = score[i];
        for (int r = 0; r < KCH; r++) {
            int bi = 0; float bv = sc[0];
            for (int i = 1; i < HD; i++) if (sc[i] > bv) { bv = sc[i]; bi = i; }
            sel[r] = bi; sc[bi] = -1e30f;
        }
        for (int a = 1; a < KCH; a++) {           // sort ascending
            int v = sel[a], p = a-1;
            while (p >= 0 && sel[p] > v) { sel[p+1] = sel[p]; p--; }
            sel[p+1] = v;
        }
        for (int i = 0; i < KCH; i++) cidx[i] = sel[i];
    }
    if (tid == 32) {
        float sc[NT];
        int sel[KSPT];
        for (int i = 0; i < NT; i++) sc[i] = tmean[i];
        for (int r = 0; r < KSPT; r++) {
            int bi = 0; float bv = sc[0];
            for (int i = 1; i < NT; i++) if (sc[i] > bv) { bv = sc[i]; bi = i; }
            sel[r] = bi; sc[bi] = -1e30f;
        }
        for (int a = 1; a < KSPT; a++) {
            int v = sel[a], p = a-1;
            while (p >= 0 && sel[p] > v) { sel[p+1] = sel[p]; p--; }
            sel[p+1] = v;
        }
        for (int i = 0; i < KSPT; i++) sidx[i] = sel[i];
    }
    __syncthreads();
    // qcha1 (Bw, 49, 128): channel = nh*16 + j
    for (int i = tid; i < NT*KCH; i += 256) {
        int t = i / KCH, j = i % KCH;
        g_qcha1[((size_t)widx*NT + t)*(CC/2) + nh*KCH + j] = qt[t*HD + cidx[j]];
    }
    // vbuf (Bw, 28, 256): channel = nh*32 + d
    for (int i = tid; i < KSPT*HD; i += 256) {
        int s = i >> 5, d = i & 31;
        g_vbuf[((size_t)widx*KSPT + s)*CC + nh*HD + d] = qt[sidx[s]*HD + d];
    }
    if (tid < KSPT) g_sidx[bn*KSPT + tid] = sidx[tid];
}

// ---------------- attention per (window, head) ----------------
__global__ void attn_kernel(const float* __restrict__ rpb) {
    int bn = blockIdx.x;
    int widx = bn >> 3, nh = bn & 7;
    __shared__ float kh[NT*KCH];     // 49x16
    __shared__ float qa[KSPT*KCH];   // 28x16
    __shared__ float vh[KSPT*HD];    // 28x32
    __shared__ float at[NT*KSPT];    // 49x28
    __shared__ float gate[NT];
    __shared__ int sidx[KSPT];
    int tid = threadIdx.x;
    if (tid < KSPT) sidx[tid] = g_sidx[bn*KSPT + tid];
    __syncthreads();
    for (int i = tid; i < NT*KCH; i += 256) {
        int t = i >> 4, j = i & 15;
        kh[i] = g_k[((size_t)widx*NT + t)*(CC/2) + nh*KCH + j];
    }
    for (int i = tid; i < KSPT*KCH; i += 256) {
        int s = i >> 4, j = i & 15;
        qa[i] = g_qcha1[((size_t)widx*NT + sidx[s])*(CC/2) + nh*KCH + j] * SCALE_F;
    }
    for (int i = tid; i < KSPT*HD; i += 256) {
        int s = i >> 5, d = i & 31;
        vh[i] = g_vproj[((size_t)widx*KSPT + s)*CC + nh*HD + d];
    }
    __syncthreads();
    for (int e = tid; e < NT*KSPT; e += 256) {
        int t = e / KSPT, s = e % KSPT;
        float sum = 0.0f;
        #pragma unroll
        for (int j = 0; j < KCH; j++) sum += kh[t*KCH + j] * qa[s*KCH + j];
        int t2 = sidx[s];
        int rel = (t/WS - t2/WS + (WS-1)) * (2*WS-1) + (t%WS - t2%WS + (WS-1));
        at[e] = sum + rpb[rel*NH + nh];
    }
    __syncthreads();
    if (tid < NT) {
        float m = -1e30f, mean = 0.0f;
        for (int s = 0; s < KSPT; s++) { float v = at[tid*KSPT + s]; m = fmaxf(m, v); mean += v; }
        gate[tid] = 1.0f / (1.0f + expf(-mean * (1.0f/KSPT)));
        float su = 0.0f;
        for (int s = 0; s < KSPT; s++) { float e2 = expf(at[tid*KSPT + s] - m); at[tid*KSPT + s] = e2; su += e2; }
        float inv = 1.0f / su;
        for (int s = 0; s < KSPT; s++) at[tid*KSPT + s] *= inv;
    }
    __syncthreads();
    for (int e = tid; e < NT*HD; e += 256) {
        int t = e >> 5, d = e & 31;
        float sum = 0.0f;
        #pragma unroll
        for (int s = 0; s < KSPT; s++) sum += at[t*KSPT + s] * vh[s*HD + d];
        g_obuf[((size_t)widx*NT + t)*CC + nh*HD + d] = sum * gate[t];
    }
}

// ---------------- window reverse + residual ----------------
__global__ void winrev_add_kernel(const float* __restrict__ x, float* __restrict__ out) {
    int row = blockIdx.x, c = threadIdx.x;
    int bidx = row / LL, l = row % LL;
    int h = l / WW, w = l % WW;
    int widx = (bidx*8 + h/WS)*8 + (w/WS);
    int token = (h%WS)*WS + (w%WS);
    out[(size_t)row*CC + c] = x[(size_t)row*CC + c] + g_xw[((size_t)widx*NT + token)*CC + c];
}

// ---------------- launch ----------------
extern "C" void kernel_launch(void* const* d_in, const int* in_sizes, int n_in,
                              void* d_out, int out_size) {
    const float* x       = (const float*)d_in[0];
    const float* norm1_g = (const float*)d_in[1];
    const float* norm1_b = (const float*)d_in[2];
    const float* wq      = (const float*)d_in[3];
    const float* bq      = (const float*)d_in[4];
    const float* wk      = (const float*)d_in[5];
    const float* bk      = (const float*)d_in[6];
    const float* wv      = (const float*)d_in[7];
    const float* bv      = (const float*)d_in[8];
    const float* wproj   = (const float*)d_in[9];
    const float* bproj   = (const float*)d_in[10];
    const float* wch     = (const float*)d_in[11];
    const float* bch     = (const float*)d_in[12];
    const float* rpb     = (const float*)d_in[13];
    const float* norm2_g = (const float*)d_in[14];
    const float* norm2_b = (const float*)d_in[15];
    const float* w1      = (const float*)d_in[16];
    const float* b1      = (const float*)d_in[17];
    const float* w2      = (const float*)d_in[18];
    const float* b2      = (const float*)d_in[19];
    float* out = (float*)d_out;

    float *p_xw, *p_q, *p_obuf, *p_qcha1, *p_k, *p_vbuf, *p_vproj, *p_h;
    cudaGetSymbolAddress((void**)&p_xw, g_xw);
    cudaGetSymbolAddress((void**)&p_q, g_q);
    cudaGetSymbolAddress((void**)&p_obuf, g_obuf);
    cudaGetSymbolAddress((void**)&p_qcha1, g_qcha1);
    cudaGetSymbolAddress((void**)&p_k, g_k);
    cudaGetSymbolAddress((void**)&p_vbuf, g_vbuf);
    cudaGetSymbolAddress((void**)&p_vproj, g_vproj);
    cudaGetSymbolAddress((void**)&p_h, g_h);

    // 1) LN1 + window partition -> g_xw
    ln1_window_kernel<<<ROWS, 256>>>(x, norm1_g, norm1_b);
    // 2) q = xw @ wq + bq -> g_q
    sgemm_kernel<0><<<dim3(CC/64, ROWS/64), 256>>>(p_xw, wq, bq, nullptr, p_q, ROWS, CC, CC);
    // 3) stats + top-k + gathers -> g_qcha1, g_vbuf, g_sidx
    topk_stats_kernel<<<BN, 256>>>(wch, bch);
    // 4) k = qcha1 @ wk + bk -> g_k
    sgemm_kernel<0><<<dim3((CC/2)/64, ROWS/64), 256>>>(p_qcha1, wk, bk, nullptr, p_k, ROWS, CC/2, CC/2);
    // 5) v = vbuf @ wv + bv -> g_vproj
    sgemm_kernel<0><<<dim3(CC/64, (BW*KSPT)/64), 256>>>(p_vbuf, wv, bv, nullptr, p_vproj, BW*KSPT, CC, CC);
    // 6) attention -> g_obuf
    attn_kernel<<<BN, 256>>>(rpb);
    // 7) proj -> g_xw (reuse)
    sgemm_kernel<0><<<dim3(CC/64, ROWS/64), 256>>>(p_obuf, wproj, bproj, nullptr, p_xw, ROWS, CC, CC);
    // 8) window reverse + residual -> d_out
    winrev_add_kernel<<<ROWS, 256>>>(x, out);
    // 9) LN2(d_out) -> g_q (reuse)
    ln2_kernel<<<ROWS, 256>>>(out, norm2_g, norm2_b);
    // 10) h = gelu(xn2 @ w1 + b1) -> g_h
    sgemm_kernel<1><<<dim3(MLPH/64, ROWS/64), 256>>>(p_q, w1, b1, nullptr, p_h, ROWS, CC, MLPH);
    // 11) out = out + h @ w2 + b2 (in-place residual)
    sgemm_kernel<0><<<dim3(CC/64, ROWS/64), 256>>>(p_h, w2, b2, out, out, ROWS, MLPH, CC);
}

// round 2
// speedup vs baseline: 2.9172x; 2.9172x over previous
#include <cuda_runtime.h>
#include <cuda_bf16.h>
#include <math.h>

// ---------------- problem constants ----------------
#define BB   32
#define HH   56
#define WW   56
#define CC   256
#define WS   7
#define NH   8
#define HD   32
#define KCH  16
#define KSPT 28
#define NT   49          // tokens per window
#define MLPH 1024
#define LL   (HH*WW)     // 3136
#define ROWS (BB*LL)     // 100352
#define BW   2048        // windows
#define BN   (BW*NH)     // 16384
#define SCALE_F 0.17677669529663687f   // 32^-0.5

// ---------------- static scratch (no allocations allowed) ----------------
__device__ float g_xw[ROWS*CC];          // windowed LN1 output; later reused as proj output
__device__ float g_q[ROWS*CC];           // q; later reused as xn2 (LN2 output)
__device__ float g_obuf[ROWS*CC];        // attention output (window layout)
__device__ float g_qcha1[BW*NT*(CC/2)];  // channel-gathered q, (Bw,49,128)
__device__ float g_k[BW*NT*(CC/2)];      // k, (Bw,49,128)
__device__ float g_vbuf[BW*KSPT*CC];     // gathered v input, (Bw,28,256)
__device__ float g_vproj[BW*KSPT*CC];    // v after projection
__device__ float g_h[ROWS*MLPH];         // MLP hidden
__device__ int   g_sidx[BN*KSPT];

// ---------------- helpers ----------------
__device__ __forceinline__ float gelu_exact(float x) {
    return 0.5f * x * (1.0f + erff(x * 0.70710678118654752f));
}

__device__ __forceinline__ float blockReduceSum256(float val) {
    __shared__ float sh[8];
    int lane = threadIdx.x & 31, wid = threadIdx.x >> 5;
    #pragma unroll
    for (int o = 16; o > 0; o >>= 1) val += __shfl_xor_sync(0xffffffffu, val, o);
    if (lane == 0) sh[wid] = val;
    __syncthreads();
    float r;
    if (wid == 0) {
        float v = (lane < 8) ? sh[lane] : 0.0f;
        #pragma unroll
        for (int o = 4; o > 0; o >>= 1) v += __shfl_xor_sync(0xffffffffu, v, o);
        if (lane == 0) sh[0] = v;
    }
    __syncthreads();
    r = sh[0];
    __syncthreads();
    return r;
}

__device__ __forceinline__ unsigned f2tf(float f) {
    unsigned r;
    asm("cvt.rna.tf32.f32 %0, %1;" : "=r"(r) : "f"(f));
    return r;
}

__device__ __forceinline__ void mma_tf32(float c[4], const unsigned a[4], const unsigned b[2]) {
    asm volatile(
        "mma.sync.aligned.m16n8k8.row.col.f32.tf32.tf32.f32 "
        "{%0,%1,%2,%3},{%4,%5,%6,%7},{%8,%9},{%0,%1,%2,%3};"
        : "+f"(c[0]), "+f"(c[1]), "+f"(c[2]), "+f"(c[3])
        : "r"(a[0]), "r"(a[1]), "r"(a[2]), "r"(a[3]), "r"(b[0]), "r"(b[1]));
}

__device__ __forceinline__ void cp_async16(void* smem_dst, const void* gmem_src) {
    unsigned saddr = (unsigned)__cvta_generic_to_shared(smem_dst);
    asm volatile("cp.async.ca.shared.global [%0], [%1], 16;\n" :: "r"(saddr), "l"(gmem_src));
}

// ---------------- LN1 + window partition ----------------
__global__ void ln1_window_kernel(const float* __restrict__ x,
                                  const float* __restrict__ g,
                                  const float* __restrict__ b) {
    int row = blockIdx.x, tid = threadIdx.x;
    float v = x[(size_t)row*CC + tid];
    float s1 = blockReduceSum256(v);
    float s2 = blockReduceSum256(v*v);
    float mu = s1 * (1.0f/CC);
    float var = s2 * (1.0f/CC) - mu*mu;
    float rstd = rsqrtf(var + 1e-5f);
    float o = (v - mu) * rstd * g[tid] + b[tid];
    int bidx = row / LL, l = row % LL;
    int h = l / WW, w = l % WW;
    int widx = (bidx*8 + h/WS)*8 + (w/WS);
    int token = (h%WS)*WS + (w%WS);
    g_xw[((size_t)widx*NT + token)*CC + tid] = o;
}

// ---------------- LN2 (plain) ----------------
__global__ void ln2_kernel(const float* __restrict__ x,
                           const float* __restrict__ g,
                           const float* __restrict__ b) {
    int row = blockIdx.x, tid = threadIdx.x;
    float v = x[(size_t)row*CC + tid];
    float s1 = blockReduceSum256(v);
    float s2 = blockReduceSum256(v*v);
    float mu = s1 * (1.0f/CC);
    float var = s2 * (1.0f/CC) - mu*mu;
    float rstd = rsqrtf(var + 1e-5f);
    g_q[(size_t)row*CC + tid] = (v - mu) * rstd * g[tid] + b[tid];
}

// ---------------- tf32 tensor-core GEMM: D = act(A@W + bias) [+ res] ----------------
// Tile 128x128x32, 8 warps (2x4), warp tile 64x32, double-buffered cp.async.
// As: m-major [128][36] (pad 4), Bs: k-major [32][136] (pad 8); both frag-load conflict-free.
// Requires M%128==0, N%128==0, K%32==0.
#define AS_STRIDE 36
#define BS_STRIDE 136
#define AS_BUF (128*AS_STRIDE)   // 4608 floats
#define BS_BUF (32*BS_STRIDE)    // 4352 floats
#define GEMM_SMEM_BYTES ((2*AS_BUF + 2*BS_BUF)*4)  // 71680

template<int ACT>  // 0 = none, 1 = gelu
__global__ void __launch_bounds__(256, 2)
gemm_tf32_kernel(const float* __restrict__ A, const float* __restrict__ Wm,
                 const float* __restrict__ bias, const float* __restrict__ res,
                 float* __restrict__ D, int M, int K, int Ncols) {
    extern __shared__ float smem[];
    float* As = smem;               // [2][128][36]
    float* Bs = smem + 2*AS_BUF;    // [2][32][136]

    int tid = threadIdx.x;
    int warp = tid >> 5, lane = tid & 31;
    int g = lane >> 2, tig = lane & 3;
    int wm = warp >> 2, wn = warp & 3;   // 2 x 4 warp grid
    int bm = blockIdx.y * 128, bn = blockIdx.x * 128;

    float acc[4][4][4];
    #pragma unroll
    for (int mi = 0; mi < 4; mi++)
        #pragma unroll
        for (int ni = 0; ni < 4; ni++)
            #pragma unroll
            for (int j = 0; j < 4; j++) acc[mi][ni][j] = 0.0f;

    int T = K >> 5;

    // issue tile t into buffer buf
    auto issue = [&](int t, int buf) {
        int k0 = t * 32;
        float* as = As + buf * AS_BUF;
        float* bs = Bs + buf * BS_BUF;
        #pragma unroll
        for (int i = 0; i < 4; i++) {
            int idx = tid + i * 256;
            int m = idx >> 3, kq = idx & 7;
            cp_async16(as + m*AS_STRIDE + kq*4, A + (size_t)(bm + m)*K + k0 + kq*4);
        }
        #pragma unroll
        for (int i = 0; i < 4; i++) {
            int idx = tid + i * 256;
            int k = idx >> 5, nq = idx & 31;
            cp_async16(bs + k*BS_STRIDE + nq*4, Wm + (size_t)(k0 + k)*Ncols + bn + nq*4);
        }
        asm volatile("cp.async.commit_group;\n" ::: "memory");
    };

    issue(0, 0);

    for (int t = 0; t < T; t++) {
        int buf = t & 1;
        if (t + 1 < T) {
            issue(t + 1, buf ^ 1);
            asm volatile("cp.async.wait_group 1;\n" ::: "memory");
        } else {
            asm volatile("cp.async.wait_group 0;\n" ::: "memory");
        }
        __syncthreads();

        const float* as = As + buf * AS_BUF;
        const float* bs = Bs + buf * BS_BUF;

        #pragma unroll
        for (int kk = 0; kk < 32; kk += 8) {
            unsigned af[4][4], bf[4][2];
            #pragma unroll
            for (int mi = 0; mi < 4; mi++) {
                int r = wm*64 + mi*16 + g;
                af[mi][0] = f2tf(as[(r    )*AS_STRIDE + kk + tig    ]);
                af[mi][1] = f2tf(as[(r + 8)*AS_STRIDE + kk + tig    ]);
                af[mi][2] = f2tf(as[(r    )*AS_STRIDE + kk + tig + 4]);
                af[mi][3] = f2tf(as[(r + 8)*AS_STRIDE + kk + tig + 4]);
            }
            #pragma unroll
            for (int ni = 0; ni < 4; ni++) {
                int c = wn*32 + ni*8 + g;
                bf[ni][0] = f2tf(bs[(kk + tig    )*BS_STRIDE + c]);
                bf[ni][1] = f2tf(bs[(kk + tig + 4)*BS_STRIDE + c]);
            }
            #pragma unroll
            for (int mi = 0; mi < 4; mi++)
                #pragma unroll
                for (int ni = 0; ni < 4; ni++)
                    mma_tf32(acc[mi][ni], af[mi], bf[ni]);
        }
        __syncthreads();
    }

    // epilogue
    #pragma unroll
    for (int mi = 0; mi < 4; mi++) {
        int r0 = bm + wm*64 + mi*16 + g;
        int r1 = r0 + 8;
        #pragma unroll
        for (int ni = 0; ni < 4; ni++) {
            int c = bn + wn*32 + ni*8 + tig*2;
            float b0 = bias[c], b1 = bias[c + 1];
            float v0 = acc[mi][ni][0] + b0;
            float v1 = acc[mi][ni][1] + b1;
            float v2 = acc[mi][ni][2] + b0;
            float v3 = acc[mi][ni][3] + b1;
            if (ACT == 1) { v0 = gelu_exact(v0); v1 = gelu_exact(v1); v2 = gelu_exact(v2); v3 = gelu_exact(v3); }
            size_t i0 = (size_t)r0*Ncols + c;
            size_t i1 = (size_t)r1*Ncols + c;
            if (res) {
                const float2 r00 = *reinterpret_cast<const float2*>(res + i0);
                const float2 r10 = *reinterpret_cast<const float2*>(res + i1);
                v0 += r00.x; v1 += r00.y; v2 += r10.x; v3 += r10.y;
            }
            *reinterpret_cast<float2*>(D + i0) = make_float2(v0, v1);
            *reinterpret_cast<float2*>(D + i1) = make_float2(v2, v3);
        }
    }
}

// ---------------- per-(window,head): stats, channel/spatial top-k, gathers ----------------
__global__ void topk_stats_kernel(const float* __restrict__ wch,
                                  const float* __restrict__ bch) {
    int bn = blockIdx.x;
    int widx = bn >> 3, nh = bn & 7;
    __shared__ float qt[NT*HD];
    __shared__ float cmean[HD], cmax[HD], tmean[NT], score[HD];
    __shared__ int cidx[KCH], sidx[KSPT];
    int tid = threadIdx.x;
    const float* qbase = g_q + (size_t)widx*NT*CC + nh*HD;
    for (int i = tid; i < NT*HD; i += 256) {
        int t = i >> 5, hd = i & 31;
        qt[i] = qbase[(size_t)t*CC + hd];
    }
    __syncthreads();
    if (tid < HD) {
        float s = 0.0f, m = -1e30f;
        for (int t = 0; t < NT; t++) { float v = qt[t*HD + tid]; s += v; m = fmaxf(m, v); }
        cmean[tid] = s * (1.0f/NT); cmax[tid] = m;
    }
    if (tid >= 64 && tid < 64 + NT) {
        int t = tid - 64;
        float s = 0.0f;
        for (int hd = 0; hd < HD; hd++) s += qt[t*HD + hd];
        tmean[t] = s * (1.0f/HD);
    }
    __syncthreads();
    if (tid < HD) {
        float s = bch[tid];
        for (int i = 0; i < HD; i++) s += cmean[i] * wch[i*HD + tid];
        for (int i = 0; i < HD; i++) s += cmax[i]  * wch[(HD+i)*HD + tid];
        score[tid] = gelu_exact(s);   // softmax before top_k is monotonic -> skip
    }
    __syncthreads();
    if (tid == 0) {
        float sc[HD];
        int sel[KCH];
        for (int i = 0; i < HD; i++) sc[i] = score[i];
        for (int r = 0; r < KCH; r++) {
            int bi = 0; float bv = sc[0];
            for (int i = 1; i < HD; i++) if (sc[i] > bv) { bv = sc[i]; bi = i; }
            sel[r] = bi; sc[bi] = -1e30f;
        }
        for (int a = 1; a < KCH; a++) {
            int v = sel[a], p = a-1;
            while (p >= 0 && sel[p] > v) { sel[p+1] = sel[p]; p--; }
            sel[p+1] = v;
        }
        for (int i = 0; i < KCH; i++) cidx[i] = sel[i];
    }
    if (tid == 32) {
        float sc[NT];
        int sel[KSPT];
        for (int i = 0; i < NT; i++) sc[i] = tmean[i];
        for (int r = 0; r < KSPT; r++) {
            int bi = 0; float bv = sc[0];
            for (int i = 1; i < NT; i++) if (sc[i] > bv) { bv = sc[i]; bi = i; }
            sel[r] = bi; sc[bi] = -1e30f;
        }
        for (int a = 1; a < KSPT; a++) {
            int v = sel[a], p = a-1;
            while (p >= 0 && sel[p] > v) { sel[p+1] = sel[p]; p--; }
            sel[p+1] = v;
        }
        for (int i = 0; i < KSPT; i++) sidx[i] = sel[i];
    }
    __syncthreads();
    // qcha1 (Bw, 49, 128): channel = nh*16 + j
    for (int i = tid; i < NT*KCH; i += 256) {
        int t = i / KCH, j = i % KCH;
        g_qcha1[((size_t)widx*NT + t)*(CC/2) + nh*KCH + j] = qt[t*HD + cidx[j]];
    }
    // vbuf (Bw, 28, 256): channel = nh*32 + d
    for (int i = tid; i < KSPT*HD; i += 256) {
        int s = i >> 5, d = i & 31;
        g_vbuf[((size_t)widx*KSPT + s)*CC + nh*HD + d] = qt[sidx[s]*HD + d];
    }
    if (tid < KSPT) g_sidx[bn*KSPT + tid] = sidx[tid];
}

// ---------------- attention per (window, head) ----------------
__global__ void attn_kernel(const float* __restrict__ rpb) {
    int bn = blockIdx.x;
    int widx = bn >> 3, nh = bn & 7;
    __shared__ float kh[NT*KCH];     // 49x16
    __shared__ float qa[KSPT*KCH];   // 28x16
    __shared__ float vh[KSPT*HD];    // 28x32
    __shared__ float at[NT*KSPT];    // 49x28
    __shared__ float gate[NT];
    __shared__ int sidx[KSPT];
    int tid = threadIdx.x;
    if (tid < KSPT) sidx[tid] = g_sidx[bn*KSPT + tid];
    __syncthreads();
    for (int i = tid; i < NT*KCH; i += 256) {
        int t = i >> 4, j = i & 15;
        kh[i] = g_k[((size_t)widx*NT + t)*(CC/2) + nh*KCH + j];
    }
    for (int i = tid; i < KSPT*KCH; i += 256) {
        int s = i >> 4, j = i & 15;
        qa[i] = g_qcha1[((size_t)widx*NT + sidx[s])*(CC/2) + nh*KCH + j] * SCALE_F;
    }
    for (int i = tid; i < KSPT*HD; i += 256) {
        int s = i >> 5, d = i & 31;
        vh[i] = g_vproj[((size_t)widx*KSPT + s)*CC + nh*HD + d];
    }
    __syncthreads();
    for (int e = tid; e < NT*KSPT; e += 256) {
        int t = e / KSPT, s = e % KSPT;
        float sum = 0.0f;
        #pragma unroll
        for (int j = 0; j < KCH; j++) sum += kh[t*KCH + j] * qa[s*KCH + j];
        int t2 = sidx[s];
        int rel = (t/WS - t2/WS + (WS-1)) * (2*WS-1) + (t%WS - t2%WS + (WS-1));
        at[e] = sum + rpb[rel*NH + nh];
    }
    __syncthreads();
    if (tid < NT) {
        float m = -1e30f, mean = 0.0f;
        for (int s = 0; s < KSPT; s++) { float v = at[tid*KSPT + s]; m = fmaxf(m, v); mean += v; }
        gate[tid] = 1.0f / (1.0f + expf(-mean * (1.0f/KSPT)));
        float su = 0.0f;
        for (int s = 0; s < KSPT; s++) { float e2 = expf(at[tid*KSPT + s] - m); at[tid*KSPT + s] = e2; su += e2; }
        float inv = 1.0f / su;
        for (int s = 0; s < KSPT; s++) at[tid*KSPT + s] *= inv;
    }
    __syncthreads();
    for (int e = tid; e < NT*HD; e += 256) {
        int t = e >> 5, d = e & 31;
        float sum = 0.0f;
        #pragma unroll
        for (int s = 0; s < KSPT; s++) sum += at[t*KSPT + s] * vh[s*HD + d];
        g_obuf[((size_t)widx*NT + t)*CC + nh*HD + d] = sum * gate[t];
    }
}

// ---------------- window reverse + residual ----------------
__global__ void winrev_add_kernel(const float* __restrict__ x, float* __restrict__ out) {
    int row = blockIdx.x, c = threadIdx.x;
    int bidx = row / LL, l = row % LL;
    int h = l / WW, w = l % WW;
    int widx = (bidx*8 + h/WS)*8 + (w/WS);
    int token = (h%WS)*WS + (w%WS);
    out[(size_t)row*CC + c] = x[(size_t)row*CC + c] + g_xw[((size_t)widx*NT + token)*CC + c];
}

// ---------------- launch ----------------
extern "C" void kernel_launch(void* const* d_in, const int* in_sizes, int n_in,
                              void* d_out, int out_size) {
    const float* x       = (const float*)d_in[0];
    const float* norm1_g = (const float*)d_in[1];
    const float* norm1_b = (const float*)d_in[2];
    const float* wq      = (const float*)d_in[3];
    const float* bq      = (const float*)d_in[4];
    const float* wk      = (const float*)d_in[5];
    const float* bk      = (const float*)d_in[6];
    const float* wv      = (const float*)d_in[7];
    const float* bv      = (const float*)d_in[8];
    const float* wproj   = (const float*)d_in[9];
    const float* bproj   = (const float*)d_in[10];
    const float* wch     = (const float*)d_in[11];
    const float* bch     = (const float*)d_in[12];
    const float* rpb     = (const float*)d_in[13];
    const float* norm2_g = (const float*)d_in[14];
    const float* norm2_b = (const float*)d_in[15];
    const float* w1      = (const float*)d_in[16];
    const float* b1      = (const float*)d_in[17];
    const float* w2      = (const float*)d_in[18];
    const float* b2      = (const float*)d_in[19];
    float* out = (float*)d_out;

    float *p_xw, *p_q, *p_obuf, *p_qcha1, *p_k, *p_vbuf, *p_vproj, *p_h;
    cudaGetSymbolAddress((void**)&p_xw, g_xw);
    cudaGetSymbolAddress((void**)&p_q, g_q);
    cudaGetSymbolAddress((void**)&p_obuf, g_obuf);
    cudaGetSymbolAddress((void**)&p_qcha1, g_qcha1);
    cudaGetSymbolAddress((void**)&p_k, g_k);
    cudaGetSymbolAddress((void**)&p_vbuf, g_vbuf);
    cudaGetSymbolAddress((void**)&p_vproj, g_vproj);
    cudaGetSymbolAddress((void**)&p_h, g_h);

    cudaFuncSetAttribute(gemm_tf32_kernel<0>, cudaFuncAttributeMaxDynamicSharedMemorySize, GEMM_SMEM_BYTES);
    cudaFuncSetAttribute(gemm_tf32_kernel<1>, cudaFuncAttributeMaxDynamicSharedMemorySize, GEMM_SMEM_BYTES);

    // 1) LN1 + window partition -> g_xw
    ln1_window_kernel<<<ROWS, 256>>>(x, norm1_g, norm1_b);
    // 2) q = xw @ wq + bq -> g_q
    gemm_tf32_kernel<0><<<dim3(CC/128, ROWS/128), 256, GEMM_SMEM_BYTES>>>(p_xw, wq, bq, nullptr, p_q, ROWS, CC, CC);
    // 3) stats + top-k + gathers -> g_qcha1, g_vbuf, g_sidx
    topk_stats_kernel<<<BN, 256>>>(wch, bch);
    // 4) k = qcha1 @ wk + bk -> g_k
    gemm_tf32_kernel<0><<<dim3((CC/2)/128, ROWS/128), 256, GEMM_SMEM_BYTES>>>(p_qcha1, wk, bk, nullptr, p_k, ROWS, CC/2, CC/2);
    // 5) v = vbuf @ wv + bv -> g_vproj
    gemm_tf32_kernel<0><<<dim3(CC/128, (BW*KSPT)/128), 256, GEMM_SMEM_BYTES>>>(p_vbuf, wv, bv, nullptr, p_vproj, BW*KSPT, CC, CC);
    // 6) attention -> g_obuf
    attn_kernel<<<BN, 256>>>(rpb);
    // 7) proj -> g_xw (reuse)
    gemm_tf32_kernel<0><<<dim3(CC/128, ROWS/128), 256, GEMM_SMEM_BYTES>>>(p_obuf, wproj, bproj, nullptr, p_xw, ROWS, CC, CC);
    // 8) window reverse + residual -> d_out
    winrev_add_kernel<<<ROWS, 256>>>(x, out);
    // 9) LN2(d_out) -> g_q (reuse)
    ln2_kernel<<<ROWS, 256>>>(out, norm2_g, norm2_b);
    // 10) h = gelu(xn2 @ w1 + b1) -> g_h
    gemm_tf32_kernel<1><<<dim3(MLPH/128, ROWS/128), 256, GEMM_SMEM_BYTES>>>(p_q, w1, b1, nullptr, p_h, ROWS, CC, MLPH);
    // 11) out = out + h @ w2 + b2 (in-place residual)
    gemm_tf32_kernel<0><<<dim3(CC/128, ROWS/128), 256, GEMM_SMEM_BYTES>>>(p_h, w2, b2, out, out, ROWS, MLPH, CC);
}

// round 5
// speedup vs baseline: 4.2991x; 1.4737x over previous
#include <cuda_runtime.h>
#include <cuda_bf16.h>
#include <math.h>
#include <stdint.h>

// ---------------- problem constants ----------------
#define BB   32
#define HH   56
#define WW   56
#define CC   256
#define WS   7
#define NH   8
#define HD   32
#define KCH  16
#define KSPT 28
#define NT   49          // tokens per window
#define MLPH 1024
#define LL   (HH*WW)     // 3136
#define ROWS (BB*LL)     // 100352
#define BW   2048        // windows
#define BN   (BW*NH)     // 16384
#define MV   (BW*KSPT)   // 57344 (v rows)
#define SCALE_F 0.17677669529663687f   // 32^-0.5

// ---------------- static scratch (no allocations allowed) ----------------
__device__ __nv_bfloat16 g_xw_bf[ROWS*CC];        // LN1 windowed (bf16) -> q gemm A
__device__ float         g_q[ROWS*CC];            // q fp32 (topk reads); reused as proj out
__device__ __nv_bfloat16 g_qcha1_bf[BW*NT*(CC/2)];// channel-gathered q (bf16) -> k gemm A, attn
__device__ float         g_k[ROWS*(CC/2)];        // k fp32 (attn reads)
__device__ __nv_bfloat16 g_vbuf_bf[MV*CC];        // gathered v input (bf16) -> v gemm A
__device__ float         g_vproj[MV*CC];          // v projected fp32 (attn reads)
__device__ __nv_bfloat16 g_obuf_bf[ROWS*CC];      // attn out (bf16) -> proj gemm A
__device__ __nv_bfloat16 g_xn2_bf[ROWS*CC];       // LN2 out (bf16) -> mlp1 A
__device__ __nv_bfloat16 g_h_bf[(size_t)ROWS*MLPH]; // mlp hidden (bf16)
__device__ int           g_sidx[BN*KSPT];
// transposed bf16 weights (N-major, K contiguous)
__device__ __nv_bfloat16 g_wq_t[CC*CC];
__device__ __nv_bfloat16 g_wk_t[(CC/2)*(CC/2)];
__device__ __nv_bfloat16 g_wv_t[CC*CC];
__device__ __nv_bfloat16 g_wproj_t[CC*CC];
__device__ __nv_bfloat16 g_w1_t[CC*MLPH];
__device__ __nv_bfloat16 g_w2_t[MLPH*CC];

// ---------------- small helpers ----------------
__device__ __forceinline__ float gelu_exact(float x) {
    return 0.5f * x * (1.0f + erff(x * 0.70710678118654752f));
}

__device__ __forceinline__ float blockReduceSum256(float val) {
    __shared__ float sh[8];
    int lane = threadIdx.x & 31, wid = threadIdx.x >> 5;
    #pragma unroll
    for (int o = 16; o > 0; o >>= 1) val += __shfl_xor_sync(0xffffffffu, val, o);
    if (lane == 0) sh[wid] = val;
    __syncthreads();
    float r;
    if (wid == 0) {
        float v = (lane < 8) ? sh[lane] : 0.0f;
        #pragma unroll
        for (int o = 4; o > 0; o >>= 1) v += __shfl_xor_sync(0xffffffffu, v, o);
        if (lane == 0) sh[0] = v;
    }
    __syncthreads();
    r = sh[0];
    __syncthreads();
    return r;
}

__device__ __forceinline__ uint32_t smem_u32(const void* p) {
    return (uint32_t)__cvta_generic_to_shared(p);
}
__device__ __forceinline__ void cp_async16(uint32_t smem_dst, const void* gmem_src) {
    asm volatile("cp.async.ca.shared.global [%0], [%1], 16;\n" :: "r"(smem_dst), "l"(gmem_src));
}
#define CP_COMMIT()  asm volatile("cp.async.commit_group;\n" ::: "memory")
#define CP_WAIT(n)   asm volatile("cp.async.wait_group %0;\n" :: "n"(n) : "memory")

__device__ __forceinline__ void mma_bf16(float c[4], const uint32_t a[4], const uint32_t b[2]) {
    asm volatile(
        "mma.sync.aligned.m16n8k16.row.col.f32.bf16.bf16.f32 "
        "{%0,%1,%2,%3},{%4,%5,%6,%7},{%8,%9},{%0,%1,%2,%3};"
        : "+f"(c[0]), "+f"(c[1]), "+f"(c[2]), "+f"(c[3])
        : "r"(a[0]), "r"(a[1]), "r"(a[2]), "r"(a[3]), "r"(b[0]), "r"(b[1]));
}

// ---------------- weight transpose+convert: Wt[n][k] = bf16(W[k][n]) ----------------
__global__ void wtrans_kernel(const float* __restrict__ W, __nv_bfloat16* __restrict__ Wt,
                              int K, int N) {
    __shared__ float t[32][33];
    int k0 = blockIdx.y * 32, n0 = blockIdx.x * 32;
    int tx = threadIdx.x, ty = threadIdx.y;   // 32 x 8
    for (int i = ty; i < 32; i += 8) t[i][tx] = W[(size_t)(k0 + i) * N + n0 + tx];
    __syncthreads();
    for (int i = ty; i < 32; i += 8)
        Wt[(size_t)(n0 + i) * K + k0 + tx] = __float2bfloat16(t[tx][i]);
}

// ---------------- bf16 HMMA GEMM: D = act(A@W + bias) [+res] ----------------
// A: M x Kt bf16 row-major. Bt: N x Kt bf16 row-major (W transposed = col-major B).
// CTA tile 128x128, K tile 32, 8 warps (2x4), warp tile 64x32, double-buffered cp.async.
// smem tiles padded to stride 40 bf16 (80B) -> fragment loads bank-conflict-free.
#define TSTR 40
template<int ACT, int OUTF32, int OUTBF>
__global__ void __launch_bounds__(256, 2)
gemm_bf16_kernel(const __nv_bfloat16* __restrict__ A, const __nv_bfloat16* __restrict__ Bt,
                 const float* __restrict__ bias, const float* __restrict__ res,
                 float* __restrict__ D, __nv_bfloat16* __restrict__ Dbf,
                 int M, int Kt, int Ncols) {
    __shared__ __nv_bfloat16 As[2][128*TSTR];
    __shared__ __nv_bfloat16 Bs[2][128*TSTR];

    int tid = threadIdx.x;
    int warp = tid >> 5, lane = tid & 31;
    int g = lane >> 2, tig = lane & 3;
    int wm = warp >> 2, wn = warp & 3;   // 2 x 4 warp grid
    int bm = blockIdx.y * 128, bn = blockIdx.x * 128;

    float acc[4][4][4];
    #pragma unroll
    for (int mi = 0; mi < 4; mi++)
        #pragma unroll
        for (int ni = 0; ni < 4; ni++)
            #pragma unroll
            for (int j = 0; j < 4; j++) acc[mi][ni][j] = 0.0f;

    int T = Kt >> 5;

    auto issue = [&](int t, int buf) {
        int k0 = t * 32;
        #pragma unroll
        for (int i = 0; i < 2; i++) {
            int idx = tid + i * 256;      // 0..511
            int r = idx >> 2, q = idx & 3;
            cp_async16(smem_u32(&As[buf][r * TSTR + q * 8]),
                       A + (size_t)(bm + r) * Kt + k0 + q * 8);
        }
        #pragma unroll
        for (int i = 0; i < 2; i++) {
            int idx = tid + i * 256;
            int r = idx >> 2, q = idx & 3;
            cp_async16(smem_u32(&Bs[buf][r * TSTR + q * 8]),
                       Bt + (size_t)(bn + r) * Kt + k0 + q * 8);
        }
        CP_COMMIT();
    };

    issue(0, 0);

    for (int t = 0; t < T; t++) {
        int buf = t & 1;
        if (t + 1 < T) {
            issue(t + 1, buf ^ 1);
            CP_WAIT(1);
        } else {
            CP_WAIT(0);
        }
        __syncthreads();

        const __nv_bfloat16* as = As[buf];
        const __nv_bfloat16* bs = Bs[buf];

        #pragma unroll
        for (int kk = 0; kk < 32; kk += 16) {
            uint32_t af[4][4], bfr[4][2];
            #pragma unroll
            for (int mi = 0; mi < 4; mi++) {
                int r = wm*64 + mi*16 + g;
                af[mi][0] = *reinterpret_cast<const uint32_t*>(&as[(r    )*TSTR + kk +     2*tig]);
                af[mi][1] = *reinterpret_cast<const uint32_t*>(&as[(r + 8)*TSTR + kk +     2*tig]);
                af[mi][2] = *reinterpret_cast<const uint32_t*>(&as[(r    )*TSTR + kk + 8 + 2*tig]);
                af[mi][3] = *reinterpret_cast<const uint32_t*>(&as[(r + 8)*TSTR + kk + 8 + 2*tig]);
            }
            #pragma unroll
            for (int ni = 0; ni < 4; ni++) {
                int c = wn*32 + ni*8 + g;
                bfr[ni][0] = *reinterpret_cast<const uint32_t*>(&bs[c*TSTR + kk +     2*tig]);
                bfr[ni][1] = *reinterpret_cast<const uint32_t*>(&bs[c*TSTR + kk + 8 + 2*tig]);
            }
            #pragma unroll
            for (int mi = 0; mi < 4; mi++)
                #pragma unroll
                for (int ni = 0; ni < 4; ni++)
                    mma_bf16(acc[mi][ni], af[mi], bfr[ni]);
        }
        __syncthreads();
    }

    // epilogue: c0,c1 -> (row g, cols 2tig..), c2,c3 -> row g+8
    #pragma unroll
    for (int mi = 0; mi < 4; mi++) {
        int r0 = bm + wm*64 + mi*16 + g;
        int r1 = r0 + 8;
        #pragma unroll
        for (int ni = 0; ni < 4; ni++) {
            int col = bn + wn*32 + ni*8 + tig*2;
            const float2 bi = *reinterpret_cast<const float2*>(bias + col);
            float v0 = acc[mi][ni][0] + bi.x;
            float v1 = acc[mi][ni][1] + bi.y;
            float v2 = acc[mi][ni][2] + bi.x;
            float v3 = acc[mi][ni][3] + bi.y;
            if (ACT == 1) { v0 = gelu_exact(v0); v1 = gelu_exact(v1); v2 = gelu_exact(v2); v3 = gelu_exact(v3); }
            size_t i0 = (size_t)r0 * Ncols + col;
            size_t i1 = (size_t)r1 * Ncols + col;
            if (res) {
                const float2 ra = *reinterpret_cast<const float2*>(res + i0);
                const float2 rb = *reinterpret_cast<const float2*>(res + i1);
                v0 += ra.x; v1 += ra.y; v2 += rb.x; v3 += rb.y;
            }
            if (OUTF32) {
                *reinterpret_cast<float2*>(D + i0) = make_float2(v0, v1);
                *reinterpret_cast<float2*>(D + i1) = make_float2(v2, v3);
            }
            if (OUTBF) {
                __nv_bfloat162 p0 = __floats2bfloat162_rn(v0, v1);
                __nv_bfloat162 p1 = __floats2bfloat162_rn(v2, v3);
                *reinterpret_cast<__nv_bfloat162*>(Dbf + i0) = p0;
                *reinterpret_cast<__nv_bfloat162*>(Dbf + i1) = p1;
            }
        }
    }
}

// ---------------- LN1 + window partition (bf16 out) ----------------
__global__ void ln1_window_kernel(const float* __restrict__ x,
                                  const float* __restrict__ g,
                                  const float* __restrict__ b) {
    int row = blockIdx.x, tid = threadIdx.x;
    float v = x[(size_t)row*CC + tid];
    float s1 = blockReduceSum256(v);
    float s2 = blockReduceSum256(v*v);
    float mu = s1 * (1.0f/CC);
    float var = s2 * (1.0f/CC) - mu*mu;
    float rstd = rsqrtf(var + 1e-5f);
    float o = (v - mu) * rstd * g[tid] + b[tid];
    int bidx = row / LL, l = row % LL;
    int h = l / WW, w = l % WW;
    int widx = (bidx*8 + h/WS)*8 + (w/WS);
    int token = (h%WS)*WS + (w%WS);
    g_xw_bf[((size_t)widx*NT + token)*CC + tid] = __float2bfloat16(o);
}

// ---------------- LN2 (bf16 out) ----------------
__global__ void ln2_kernel(const float* __restrict__ x,
                           const float* __restrict__ g,
                           const float* __restrict__ b) {
    int row = blockIdx.x, tid = threadIdx.x;
    float v = x[(size_t)row*CC + tid];
    float s1 = blockReduceSum256(v);
    float s2 = blockReduceSum256(v*v);
    float mu = s1 * (1.0f/CC);
    float var = s2 * (1.0f/CC) - mu*mu;
    float rstd = rsqrtf(var + 1e-5f);
    g_xn2_bf[(size_t)row*CC + tid] = __float2bfloat16((v - mu) * rstd * g[tid] + b[tid]);
}

// ---------------- per-(window,head): stats, parallel top-k, gathers ----------------
__global__ void topk_stats_kernel(const float* __restrict__ wch,
                                  const float* __restrict__ bch) {
    int bn = blockIdx.x;
    int widx = bn >> 3, nh = bn & 7;
    __shared__ float qt[NT*HD];
    __shared__ float cmean[HD], cmax[HD], tmean[NT], score[HD];
    __shared__ int cflag[HD], sflag[NT];
    __shared__ int cidx[KCH], sidx[KSPT];
    int tid = threadIdx.x;
    const float* qbase = g_q + (size_t)widx*NT*CC + nh*HD;
    for (int i = tid; i < NT*HD; i += 256) {
        int t = i >> 5, hd = i & 31;
        qt[i] = qbase[(size_t)t*CC + hd];
    }
    __syncthreads();
    if (tid < HD) {
        float s = 0.0f, m = -1e30f;
        for (int t = 0; t < NT; t++) { float v = qt[t*HD + tid]; s += v; m = fmaxf(m, v); }
        cmean[tid] = s * (1.0f/NT); cmax[tid] = m;
    }
    if (tid >= 64 && tid < 64 + NT) {
        int t = tid - 64;
        float s = 0.0f;
        for (int hd = 0; hd < HD; hd++) s += qt[t*HD + hd];
        tmean[t] = s * (1.0f/HD);
    }
    __syncthreads();
    if (tid < HD) {
        float s = bch[tid];
        for (int i = 0; i < HD; i++) s += cmean[i] * wch[i*HD + tid];
        for (int i = 0; i < HD; i++) s += cmax[i]  * wch[(HD+i)*HD + tid];
        score[tid] = gelu_exact(s);   // softmax before top_k is monotonic -> skip
    }
    __syncthreads();
    // parallel stable top-k by rank counting (matches lax.top_k tie rule + sort)
    if (tid < HD) {
        float si = score[tid];
        int cnt = 0;
        #pragma unroll
        for (int j = 0; j < HD; j++) {
            float sj = score[j];
            cnt += (sj > si) || (sj == si && j < tid);
        }
        cflag[tid] = (cnt < KCH) ? 1 : 0;
    }
    if (tid >= 64 && tid < 64 + NT) {
        int t = tid - 64;
        float si = tmean[t];
        int cnt = 0;
        #pragma unroll
        for (int j = 0; j < NT; j++) {
            float sj = tmean[j];
            cnt += (sj > si) || (sj == si && j < t);
        }
        sflag[t] = (cnt < KSPT) ? 1 : 0;
    }
    __syncthreads();
    if (tid < HD && cflag[tid]) {
        int pos = 0;
        for (int j = 0; j < tid; j++) pos += cflag[j];
        cidx[pos] = tid;
    }
    if (tid >= 64 && tid < 64 + NT && sflag[tid - 64]) {
        int t = tid - 64, pos = 0;
        for (int j = 0; j < t; j++) pos += sflag[j];
        sidx[pos] = t;
    }
    __syncthreads();
    for (int i = tid; i < NT*KCH; i += 256) {
        int t = i / KCH, j = i % KCH;
        g_qcha1_bf[((size_t)widx*NT + t)*(CC/2) + nh*KCH + j] = __float2bfloat16(qt[t*HD + cidx[j]]);
    }
    for (int i = tid; i < KSPT*HD; i += 256) {
        int s = i >> 5, d = i & 31;
        g_vbuf_bf[((size_t)widx*KSPT + s)*CC + nh*HD + d] = __float2bfloat16(qt[sidx[s]*HD + d]);
    }
    if (tid < KSPT) g_sidx[bn*KSPT + tid] = sidx[tid];
}

// ---------------- attention per (window, head) ----------------
__global__ void attn_kernel(const float* __restrict__ rpb) {
    int bn = blockIdx.x;
    int widx = bn >> 3, nh = bn & 7;
    __shared__ float kh[NT*KCH];     // 49x16
    __shared__ float qa[KSPT*KCH];   // 28x16
    __shared__ float vh[KSPT*HD];    // 28x32
    __shared__ float at[NT*KSPT];    // 49x28
    __shared__ float gate[NT];
    __shared__ int sidx[KSPT];
    int tid = threadIdx.x;
    if (tid < KSPT) sidx[tid] = g_sidx[bn*KSPT + tid];
    __syncthreads();
    for (int i = tid; i < NT*KCH; i += 256) {
        int t = i >> 4, j = i & 15;
        kh[i] = g_k[((size_t)widx*NT + t)*(CC/2) + nh*KCH + j];
    }
    for (int i = tid; i < KSPT*KCH; i += 256) {
        int s = i >> 4, j = i & 15;
        qa[i] = __bfloat162float(g_qcha1_bf[((size_t)widx*NT + sidx[s])*(CC/2) + nh*KCH + j]) * SCALE_F;
    }
    for (int i = tid; i < KSPT*HD; i += 256) {
        int s = i >> 5, d = i & 31;
        vh[i] = g_vproj[((size_t)widx*KSPT + s)*CC + nh*HD + d];
    }
    __syncthreads();
    for (int e = tid; e < NT*KSPT; e += 256) {
        int t = e / KSPT, s = e % KSPT;
        float sum = 0.0f;
        #pragma unroll
        for (int j = 0; j < KCH; j++) sum += kh[t*KCH + j] * qa[s*KCH + j];
        int t2 = sidx[s];
        int rel = (t/WS - t2/WS + (WS-1)) * (2*WS-1) + (t%WS - t2%WS + (WS-1));
        at[e] = sum + rpb[rel*NH + nh];
    }
    __syncthreads();
    if (tid < NT) {
        float m = -1e30f, mean = 0.0f;
        for (int s = 0; s < KSPT; s++) { float v = at[tid*KSPT + s]; m = fmaxf(m, v); mean += v; }
        gate[tid] = 1.0f / (1.0f + expf(-mean * (1.0f/KSPT)));
        float su = 0.0f;
        for (int s = 0; s < KSPT; s++) { float e2 = expf(at[tid*KSPT + s] - m); at[tid*KSPT + s] = e2; su += e2; }
        float inv = 1.0f / su;
        for (int s = 0; s < KSPT; s++) at[tid*KSPT + s] *= inv;
    }
    __syncthreads();
    for (int e = tid; e < NT*HD; e += 256) {
        int t = e >> 5, d = e & 31;
        float sum = 0.0f;
        #pragma unroll
        for (int s = 0; s < KSPT; s++) sum += at[t*KSPT + s] * vh[s*HD + d];
        g_obuf_bf[((size_t)widx*NT + t)*CC + nh*HD + d] = __float2bfloat16(sum * gate[t]);
    }
}

// ---------------- window reverse + residual ----------------
__global__ void winrev_add_kernel(const float* __restrict__ x, float* __restrict__ out) {
    int row = blockIdx.x, c = threadIdx.x;
    int bidx = row / LL, l = row % LL;
    int h = l / WW, w = l % WW;
    int widx = (bidx*8 + h/WS)*8 + (w/WS);
    int token = (h%WS)*WS + (w%WS);
    out[(size_t)row*CC + c] = x[(size_t)row*CC + c] + g_q[((size_t)widx*NT + token)*CC + c];
}

// ---------------- launch ----------------
extern "C" void kernel_launch(void* const* d_in, const int* in_sizes, int n_in,
                              void* d_out, int out_size) {
    const float* x       = (const float*)d_in[0];
    const float* norm1_g = (const float*)d_in[1];
    const float* norm1_b = (const float*)d_in[2];
    const float* wq      = (const float*)d_in[3];
    const float* bq      = (const float*)d_in[4];
    const float* wk      = (const float*)d_in[5];
    const float* bk      = (const float*)d_in[6];
    const float* wv      = (const float*)d_in[7];
    const float* bv      = (const float*)d_in[8];
    const float* wproj   = (const float*)d_in[9];
    const float* bproj   = (const float*)d_in[10];
    const float* wch     = (const float*)d_in[11];
    const float* bch     = (const float*)d_in[12];
    const float* rpb     = (const float*)d_in[13];
    const float* norm2_g = (const float*)d_in[14];
    const float* norm2_b = (const float*)d_in[15];
    const float* w1      = (const float*)d_in[16];
    const float* b1      = (const float*)d_in[17];
    const float* w2      = (const float*)d_in[18];
    const float* b2      = (const float*)d_in[19];
    float* out = (float*)d_out;

    __nv_bfloat16 *p_xw_bf, *p_qcha1_bf, *p_vbuf_bf, *p_obuf_bf, *p_xn2_bf, *p_h_bf;
    __nv_bfloat16 *p_wq_t, *p_wk_t, *p_wv_t, *p_wproj_t, *p_w1_t, *p_w2_t;
    float *p_q, *p_k, *p_vproj;
    cudaGetSymbolAddress((void**)&p_xw_bf, g_xw_bf);
    cudaGetSymbolAddress((void**)&p_q, g_q);
    cudaGetSymbolAddress((void**)&p_qcha1_bf, g_qcha1_bf);
    cudaGetSymbolAddress((void**)&p_k, g_k);
    cudaGetSymbolAddress((void**)&p_vbuf_bf, g_vbuf_bf);
    cudaGetSymbolAddress((void**)&p_vproj, g_vproj);
    cudaGetSymbolAddress((void**)&p_obuf_bf, g_obuf_bf);
    cudaGetSymbolAddress((void**)&p_xn2_bf, g_xn2_bf);
    cudaGetSymbolAddress((void**)&p_h_bf, g_h_bf);
    cudaGetSymbolAddress((void**)&p_wq_t, g_wq_t);
    cudaGetSymbolAddress((void**)&p_wk_t, g_wk_t);
    cudaGetSymbolAddress((void**)&p_wv_t, g_wv_t);
    cudaGetSymbolAddress((void**)&p_wproj_t, g_wproj_t);
    cudaGetSymbolAddress((void**)&p_w1_t, g_w1_t);
    cudaGetSymbolAddress((void**)&p_w2_t, g_w2_t);

    dim3 tb(32, 8);
    // weight transpose+convert
    wtrans_kernel<<<dim3(CC/32, CC/32), tb>>>(wq, p_wq_t, CC, CC);
    wtrans_kernel<<<dim3((CC/2)/32, (CC/2)/32), tb>>>(wk, p_wk_t, CC/2, CC/2);
    wtrans_kernel<<<dim3(CC/32, CC/32), tb>>>(wv, p_wv_t, CC, CC);
    wtrans_kernel<<<dim3(CC/32, CC/32), tb>>>(wproj, p_wproj_t, CC, CC);
    wtrans_kernel<<<dim3(MLPH/32, CC/32), tb>>>(w1, p_w1_t, CC, MLPH);
    wtrans_kernel<<<dim3(CC/32, MLPH/32), tb>>>(w2, p_w2_t, MLPH, CC);

    // 1) LN1 + window partition -> g_xw_bf
    ln1_window_kernel<<<ROWS, 256>>>(x, norm1_g, norm1_b);
    // 2) q = xw @ wq + bq -> g_q (fp32)
    gemm_bf16_kernel<0,1,0><<<dim3(CC/128, ROWS/128), 256>>>(
        p_xw_bf, p_wq_t, bq, nullptr, p_q, nullptr, ROWS, CC, CC);
    // 3) top-k + gathers
    topk_stats_kernel<<<BN, 256>>>(wch, bch);
    // 4) k = qcha1 @ wk + bk -> g_k (fp32)
    gemm_bf16_kernel<0,1,0><<<dim3((CC/2)/128, ROWS/128), 256>>>(
        p_qcha1_bf, p_wk_t, bk, nullptr, p_k, nullptr, ROWS, CC/2, CC/2);
    // 5) v = vbuf @ wv + bv -> g_vproj (fp32)
    gemm_bf16_kernel<0,1,0><<<dim3(CC/128, MV/128), 256>>>(
        p_vbuf_bf, p_wv_t, bv, nullptr, p_vproj, nullptr, MV, CC, CC);
    // 6) attention -> g_obuf_bf
    attn_kernel<<<BN, 256>>>(rpb);
    // 7) proj -> g_q (fp32, reuse)
    gemm_bf16_kernel<0,1,0><<<dim3(CC/128, ROWS/128), 256>>>(
        p_obuf_bf, p_wproj_t, bproj, nullptr, p_q, nullptr, ROWS, CC, CC);
    // 8) window reverse + residual -> d_out
    winrev_add_kernel<<<ROWS, 256>>>(x, out);
    // 9) LN2(d_out) -> g_xn2_bf
    ln2_kernel<<<ROWS, 256>>>(out, norm2_g, norm2_b);
    // 10) h = gelu(xn2 @ w1 + b1) -> g_h_bf (bf16 only)
    gemm_bf16_kernel<1,0,1><<<dim3(MLPH/128, ROWS/128), 256>>>(
        p_xn2_bf, p_w1_t, b1, nullptr, nullptr, p_h_bf, ROWS, CC, MLPH);
    // 11) out = out + h @ w2 + b2
    gemm_bf16_kernel<0,1,0><<<dim3(CC/128, ROWS/128), 256>>>(
        p_h_bf, p_w2_t, b2, out, out, nullptr, ROWS, MLPH, CC);
}

// round 6
// speedup vs baseline: 4.4389x; 1.0325x over previous
#include <cuda_runtime.h>
#include <cuda_bf16.h>
#include <math.h>
#include <stdint.h>

// ---------------- problem constants ----------------
#define BB   32
#define HH   56
#define WW   56
#define CC   256
#define WS   7
#define NH   8
#define HD   32
#define KCH  16
#define KSPT 28
#define NT   49          // tokens per window
#define MLPH 1024
#define LL   (HH*WW)     // 3136
#define ROWS (BB*LL)     // 100352
#define BW   2048        // windows
#define BN   (BW*NH)     // 16384
#define MV   (BW*KSPT)   // 57344 (v rows)
#define SCALE_F 0.17677669529663687f   // 32^-0.5

// ---------------- static scratch (no allocations allowed) ----------------
__device__ __nv_bfloat16 g_xw_bf[ROWS*CC];        // LN1 windowed (bf16) -> q gemm A
__device__ float         g_q[ROWS*CC];            // q fp32 (topk reads)
__device__ __nv_bfloat16 g_qcha1_bf[BW*NT*(CC/2)];// channel-gathered q (bf16) -> k gemm A, attn
__device__ __nv_bfloat16 g_k_bf[ROWS*(CC/2)];     // k bf16 (attn reads)
__device__ __nv_bfloat16 g_vbuf_bf[MV*CC];        // gathered v input (bf16) -> v gemm A
__device__ __nv_bfloat16 g_vproj_bf[MV*CC];       // v projected bf16 (attn reads)
__device__ __nv_bfloat16 g_obuf_bf[ROWS*CC];      // attn out (bf16) -> proj gemm A
__device__ __nv_bfloat16 g_xn2_bf[ROWS*CC];       // LN2 out (bf16) -> mlp1 A
__device__ __nv_bfloat16 g_h_bf[(size_t)ROWS*MLPH]; // mlp hidden (bf16)
__device__ int           g_sidx[BN*KSPT];
// transposed bf16 weights (N-major, K contiguous)
__device__ __nv_bfloat16 g_wq_t[CC*CC];
__device__ __nv_bfloat16 g_wk_t[(CC/2)*(CC/2)];
__device__ __nv_bfloat16 g_wv_t[CC*CC];
__device__ __nv_bfloat16 g_wproj_t[CC*CC];
__device__ __nv_bfloat16 g_w1_t[CC*MLPH];
__device__ __nv_bfloat16 g_w2_t[MLPH*CC];

// ---------------- small helpers ----------------
__device__ __forceinline__ float gelu_exact(float x) {
    return 0.5f * x * (1.0f + erff(x * 0.70710678118654752f));
}

__device__ __forceinline__ float blockReduceSum256(float val) {
    __shared__ float sh[8];
    int lane = threadIdx.x & 31, wid = threadIdx.x >> 5;
    #pragma unroll
    for (int o = 16; o > 0; o >>= 1) val += __shfl_xor_sync(0xffffffffu, val, o);
    if (lane == 0) sh[wid] = val;
    __syncthreads();
    float r;
    if (wid == 0) {
        float v = (lane < 8) ? sh[lane] : 0.0f;
        #pragma unroll
        for (int o = 4; o > 0; o >>= 1) v += __shfl_xor_sync(0xffffffffu, v, o);
        if (lane == 0) sh[0] = v;
    }
    __syncthreads();
    r = sh[0];
    __syncthreads();
    return r;
}

__device__ __forceinline__ uint32_t smem_u32(const void* p) {
    return (uint32_t)__cvta_generic_to_shared(p);
}
__device__ __forceinline__ void cp_async16(uint32_t smem_dst, const void* gmem_src) {
    asm volatile("cp.async.ca.shared.global [%0], [%1], 16;\n" :: "r"(smem_dst), "l"(gmem_src));
}
#define CP_COMMIT()  asm volatile("cp.async.commit_group;\n" ::: "memory")
#define CP_WAIT(n)   asm volatile("cp.async.wait_group %0;\n" :: "n"(n) : "memory")

__device__ __forceinline__ void mma_bf16(float c[4], const uint32_t a[4], const uint32_t b[2]) {
    asm volatile(
        "mma.sync.aligned.m16n8k16.row.col.f32.bf16.bf16.f32 "
        "{%0,%1,%2,%3},{%4,%5,%6,%7},{%8,%9},{%0,%1,%2,%3};"
        : "+f"(c[0]), "+f"(c[1]), "+f"(c[2]), "+f"(c[3])
        : "r"(a[0]), "r"(a[1]), "r"(a[2]), "r"(a[3]), "r"(b[0]), "r"(b[1]));
}

// window-layout row -> (B, H*W) row
__device__ __forceinline__ int winrev_row(int wr) {
    int widx = wr / NT, token = wr % NT;
    int b = widx >> 6, rem = widx & 63;
    int wh = rem >> 3, ww = rem & 7;
    int h = wh * WS + token / WS;
    int w = ww * WS + token % WS;
    return b * LL + h * WW + w;
}

// ---------------- fused weight transpose+convert (all 6 weights, 1 launch) ----------------
__global__ void wtrans_all_kernel(
    const float* __restrict__ wq, __nv_bfloat16* __restrict__ wqt,
    const float* __restrict__ wk, __nv_bfloat16* __restrict__ wkt,
    const float* __restrict__ wv, __nv_bfloat16* __restrict__ wvt,
    const float* __restrict__ wp, __nv_bfloat16* __restrict__ wpt,
    const float* __restrict__ w1, __nv_bfloat16* __restrict__ w1t,
    const float* __restrict__ w2, __nv_bfloat16* __restrict__ w2t) {
    __shared__ float t[32][33];
    int bid = blockIdx.x;
    const float* W; __nv_bfloat16* Wt; int K, N, local;
    if      (bid < 64)  { W = wq; Wt = wqt; K = 256;  N = 256;  local = bid; }
    else if (bid < 80)  { W = wk; Wt = wkt; K = 128;  N = 128;  local = bid - 64; }
    else if (bid < 144) { W = wv; Wt = wvt; K = 256;  N = 256;  local = bid - 80; }
    else if (bid < 208) { W = wp; Wt = wpt; K = 256;  N = 256;  local = bid - 144; }
    else if (bid < 464) { W = w1; Wt = w1t; K = 256;  N = 1024; local = bid - 208; }
    else                { W = w2; Wt = w2t; K = 1024; N = 256;  local = bid - 464; }
    int tpx = N >> 5;
    int txi = local % tpx, tyi = local / tpx;
    int k0 = tyi * 32, n0 = txi * 32;
    int tx = threadIdx.x, ty = threadIdx.y;   // 32 x 8
    for (int i = ty; i < 32; i += 8) t[i][tx] = W[(size_t)(k0 + i) * N + n0 + tx];
    __syncthreads();
    for (int i = ty; i < 32; i += 8)
        Wt[(size_t)(n0 + i) * K + k0 + tx] = __float2bfloat16(t[tx][i]);
}

// ---------------- bf16 HMMA GEMM: D = act(A@W + bias) [+res], optional winrev remap ----------------
// A: M x Kt bf16 row-major. Bt: N x Kt bf16 row-major (W transposed = col-major B).
// CTA tile 128x128, K tile 64, 8 warps (2x4), warp tile 64x32, double-buffered cp.async.
#define TSTR 72
#define TBUF (128*TSTR)
#define GEMM_SMEM (4*TBUF*2)   // 73728 bytes (As0,As1,Bs0,Bs1)

template<int ACT, int OUTF32, int OUTBF, int WREV>
__global__ void __launch_bounds__(256, 2)
gemm_bf16_kernel(const __nv_bfloat16* __restrict__ A, const __nv_bfloat16* __restrict__ Bt,
                 const float* __restrict__ bias, const float* __restrict__ res,
                 float* __restrict__ D, __nv_bfloat16* __restrict__ Dbf,
                 int M, int Kt, int Ncols) {
    extern __shared__ __nv_bfloat16 sm[];
    __nv_bfloat16* As[2] = { sm, sm + TBUF };
    __nv_bfloat16* Bs[2] = { sm + 2*TBUF, sm + 3*TBUF };

    int tid = threadIdx.x;
    int warp = tid >> 5, lane = tid & 31;
    int g = lane >> 2, tig = lane & 3;
    int wm = warp >> 2, wn = warp & 3;   // 2 x 4 warp grid
    int bm = blockIdx.y * 128, bn = blockIdx.x * 128;

    float acc[4][4][4];
    #pragma unroll
    for (int mi = 0; mi < 4; mi++)
        #pragma unroll
        for (int ni = 0; ni < 4; ni++)
            #pragma unroll
            for (int j = 0; j < 4; j++) acc[mi][ni][j] = 0.0f;

    int T = Kt >> 6;

    auto issue = [&](int t, int buf) {
        int k0 = t << 6;
        #pragma unroll
        for (int i = 0; i < 4; i++) {
            int idx = tid + i * 256;      // 0..1023
            int r = idx >> 3, q = idx & 7;
            cp_async16(smem_u32(&As[buf][r * TSTR + q * 8]),
                       A + (size_t)(bm + r) * Kt + k0 + q * 8);
        }
        #pragma unroll
        for (int i = 0; i < 4; i++) {
            int idx = tid + i * 256;
            int r = idx >> 3, q = idx & 7;
            cp_async16(smem_u32(&Bs[buf][r * TSTR + q * 8]),
                       Bt + (size_t)(bn + r) * Kt + k0 + q * 8);
        }
        CP_COMMIT();
    };

    issue(0, 0);

    for (int t = 0; t < T; t++) {
        int buf = t & 1;
        if (t + 1 < T) {
            issue(t + 1, buf ^ 1);
            CP_WAIT(1);
        } else {
            CP_WAIT(0);
        }
        __syncthreads();

        const __nv_bfloat16* as = As[buf];
        const __nv_bfloat16* bs = Bs[buf];

        #pragma unroll
        for (int kk = 0; kk < 64; kk += 16) {
            uint32_t af[4][4], bfr[4][2];
            #pragma unroll
            for (int mi = 0; mi < 4; mi++) {
                int r = wm*64 + mi*16 + g;
                af[mi][0] = *reinterpret_cast<const uint32_t*>(&as[(r    )*TSTR + kk +     2*tig]);
                af[mi][1] = *reinterpret_cast<const uint32_t*>(&as[(r + 8)*TSTR + kk +     2*tig]);
                af[mi][2] = *reinterpret_cast<const uint32_t*>(&as[(r    )*TSTR + kk + 8 + 2*tig]);
                af[mi][3] = *reinterpret_cast<const uint32_t*>(&as[(r + 8)*TSTR + kk + 8 + 2*tig]);
            }
            #pragma unroll
            for (int ni = 0; ni < 4; ni++) {
                int c = wn*32 + ni*8 + g;
                bfr[ni][0] = *reinterpret_cast<const uint32_t*>(&bs[c*TSTR + kk +     2*tig]);
                bfr[ni][1] = *reinterpret_cast<const uint32_t*>(&bs[c*TSTR + kk + 8 + 2*tig]);
            }
            #pragma unroll
            for (int mi = 0; mi < 4; mi++)
                #pragma unroll
                for (int ni = 0; ni < 4; ni++)
                    mma_bf16(acc[mi][ni], af[mi], bfr[ni]);
        }
        __syncthreads();
    }

    // epilogue: c0,c1 -> (row g, cols 2tig..), c2,c3 -> row g+8
    #pragma unroll
    for (int mi = 0; mi < 4; mi++) {
        int r0 = bm + wm*64 + mi*16 + g;
        int r1 = r0 + 8;
        int o0 = WREV ? winrev_row(r0) : r0;
        int o1 = WREV ? winrev_row(r1) : r1;
        #pragma unroll
        for (int ni = 0; ni < 4; ni++) {
            int col = bn + wn*32 + ni*8 + tig*2;
            const float2 bi = *reinterpret_cast<const float2*>(bias + col);
            float v0 = acc[mi][ni][0] + bi.x;
            float v1 = acc[mi][ni][1] + bi.y;
            float v2 = acc[mi][ni][2] + bi.x;
            float v3 = acc[mi][ni][3] + bi.y;
            if (ACT == 1) { v0 = gelu_exact(v0); v1 = gelu_exact(v1); v2 = gelu_exact(v2); v3 = gelu_exact(v3); }
            size_t i0 = (size_t)o0 * Ncols + col;
            size_t i1 = (size_t)o1 * Ncols + col;
            if (res) {
                const float2 ra = *reinterpret_cast<const float2*>(res + i0);
                const float2 rb = *reinterpret_cast<const float2*>(res + i1);
                v0 += ra.x; v1 += ra.y; v2 += rb.x; v3 += rb.y;
            }
            if (OUTF32) {
                *reinterpret_cast<float2*>(D + i0) = make_float2(v0, v1);
                *reinterpret_cast<float2*>(D + i1) = make_float2(v2, v3);
            }
            if (OUTBF) {
                __nv_bfloat162 p0 = __floats2bfloat162_rn(v0, v1);
                __nv_bfloat162 p1 = __floats2bfloat162_rn(v2, v3);
                *reinterpret_cast<__nv_bfloat162*>(Dbf + i0) = p0;
                *reinterpret_cast<__nv_bfloat162*>(Dbf + i1) = p1;
            }
        }
    }
}

// ---------------- LN1 + window partition (bf16 out) ----------------
__global__ void ln1_window_kernel(const float* __restrict__ x,
                                  const float* __restrict__ g,
                                  const float* __restrict__ b) {
    int row = blockIdx.x, tid = threadIdx.x;
    float v = x[(size_t)row*CC + tid];
    float s1 = blockReduceSum256(v);
    float s2 = blockReduceSum256(v*v);
    float mu = s1 * (1.0f/CC);
    float var = s2 * (1.0f/CC) - mu*mu;
    float rstd = rsqrtf(var + 1e-5f);
    float o = (v - mu) * rstd * g[tid] + b[tid];
    int bidx = row / LL, l = row % LL;
    int h = l / WW, w = l % WW;
    int widx = (bidx*8 + h/WS)*8 + (w/WS);
    int token = (h%WS)*WS + (w%WS);
    g_xw_bf[((size_t)widx*NT + token)*CC + tid] = __float2bfloat16(o);
}

// ---------------- LN2 (bf16 out) ----------------
__global__ void ln2_kernel(const float* __restrict__ x,
                           const float* __restrict__ g,
                           const float* __restrict__ b) {
    int row = blockIdx.x, tid = threadIdx.x;
    float v = x[(size_t)row*CC + tid];
    float s1 = blockReduceSum256(v);
    float s2 = blockReduceSum256(v*v);
    float mu = s1 * (1.0f/CC);
    float var = s2 * (1.0f/CC) - mu*mu;
    float rstd = rsqrtf(var + 1e-5f);
    g_xn2_bf[(size_t)row*CC + tid] = __float2bfloat16((v - mu) * rstd * g[tid] + b[tid]);
}

// ---------------- per-(window,head): stats, parallel top-k, gathers ----------------
__global__ void topk_stats_kernel(const float* __restrict__ wch,
                                  const float* __restrict__ bch) {
    int bn = blockIdx.x;
    int widx = bn >> 3, nh = bn & 7;
    __shared__ float qt[NT*HD];
    __shared__ float cmean[HD], cmax[HD], tmean[NT], score[HD];
    __shared__ int cflag[HD], sflag[NT];
    __shared__ int cidx[KCH], sidx[KSPT];
    int tid = threadIdx.x;
    const float* qbase = g_q + (size_t)widx*NT*CC + nh*HD;
    for (int i = tid; i < NT*HD; i += 256) {
        int t = i >> 5, hd = i & 31;
        qt[i] = qbase[(size_t)t*CC + hd];
    }
    __syncthreads();
    if (tid < HD) {
        float s = 0.0f, m = -1e30f;
        for (int t = 0; t < NT; t++) { float v = qt[t*HD + tid]; s += v; m = fmaxf(m, v); }
        cmean[tid] = s * (1.0f/NT); cmax[tid] = m;
    }
    if (tid >= 64 && tid < 64 + NT) {
        int t = tid - 64;
        float s = 0.0f;
        for (int hd = 0; hd < HD; hd++) s += qt[t*HD + hd];
        tmean[t] = s * (1.0f/HD);
    }
    __syncthreads();
    if (tid < HD) {
        float s = bch[tid];
        for (int i = 0; i < HD; i++) s += cmean[i] * wch[i*HD + tid];
        for (int i = 0; i < HD; i++) s += cmax[i]  * wch[(HD+i)*HD + tid];
        score[tid] = gelu_exact(s);   // softmax before top_k is monotonic -> skip
    }
    __syncthreads();
    // parallel stable top-k by rank counting (matches lax.top_k tie rule + sort)
    if (tid < HD) {
        float si = score[tid];
        int cnt = 0;
        #pragma unroll
        for (int j = 0; j < HD; j++) {
            float sj = score[j];
            cnt += (sj > si) || (sj == si && j < tid);
        }
        cflag[tid] = (cnt < KCH) ? 1 : 0;
    }
    if (tid >= 64 && tid < 64 + NT) {
        int t = tid - 64;
        float si = tmean[t];
        int cnt = 0;
        #pragma unroll
        for (int j = 0; j < NT; j++) {
            float sj = tmean[j];
            cnt += (sj > si) || (sj == si && j < t);
        }
        sflag[t] = (cnt < KSPT) ? 1 : 0;
    }
    __syncthreads();
    if (tid < HD && cflag[tid]) {
        int pos = 0;
        for (int j = 0; j < tid; j++) pos += cflag[j];
        cidx[pos] = tid;
    }
    if (tid >= 64 && tid < 64 + NT && sflag[tid - 64]) {
        int t = tid - 64, pos = 0;
        for (int j = 0; j < t; j++) pos += sflag[j];
        sidx[pos] = t;
    }
    __syncthreads();
    for (int i = tid; i < NT*KCH; i += 256) {
        int t = i / KCH, j = i % KCH;
        g_qcha1_bf[((size_t)widx*NT + t)*(CC/2) + nh*KCH + j] = __float2bfloat16(qt[t*HD + cidx[j]]);
    }
    for (int i = tid; i < KSPT*HD; i += 256) {
        int s = i >> 5, d = i & 31;
        g_vbuf_bf[((size_t)widx*KSPT + s)*CC + nh*HD + d] = __float2bfloat16(qt[sidx[s]*HD + d]);
    }
    if (tid < KSPT) g_sidx[bn*KSPT + tid] = sidx[tid];
}

// ---------------- attention per (window, head) ----------------
__global__ void attn_kernel(const float* __restrict__ rpb) {
    int bn = blockIdx.x;
    int widx = bn >> 3, nh = bn & 7;
    __shared__ float kh[NT*KCH];     // 49x16
    __shared__ float qa[KSPT*KCH];   // 28x16
    __shared__ float vh[KSPT*HD];    // 28x32
    __shared__ float at[NT*KSPT];    // 49x28
    __shared__ float gate[NT];
    __shared__ int sidx[KSPT];
    int tid = threadIdx.x;
    if (tid < KSPT) sidx[tid] = g_sidx[bn*KSPT + tid];
    __syncthreads();
    for (int i = tid; i < NT*KCH; i += 256) {
        int t = i >> 4, j = i & 15;
        kh[i] = __bfloat162float(g_k_bf[((size_t)widx*NT + t)*(CC/2) + nh*KCH + j]);
    }
    for (int i = tid; i < KSPT*KCH; i += 256) {
        int s = i >> 4, j = i & 15;
        qa[i] = __bfloat162float(g_qcha1_bf[((size_t)widx*NT + sidx[s])*(CC/2) + nh*KCH + j]) * SCALE_F;
    }
    for (int i = tid; i < KSPT*HD; i += 256) {
        int s = i >> 5, d = i & 31;
        vh[i] = __bfloat162float(g_vproj_bf[((size_t)widx*KSPT + s)*CC + nh*HD + d]);
    }
    __syncthreads();
    for (int e = tid; e < NT*KSPT; e += 256) {
        int t = e / KSPT, s = e % KSPT;
        float sum = 0.0f;
        #pragma unroll
        for (int j = 0; j < KCH; j++) sum += kh[t*KCH + j] * qa[s*KCH + j];
        int t2 = sidx[s];
        int rel = (t/WS - t2/WS + (WS-1)) * (2*WS-1) + (t%WS - t2%WS + (WS-1));
        at[e] = sum + rpb[rel*NH + nh];
    }
    __syncthreads();
    if (tid < NT) {
        float m = -1e30f, mean = 0.0f;
        for (int s = 0; s < KSPT; s++) { float v = at[tid*KSPT + s]; m = fmaxf(m, v); mean += v; }
        gate[tid] = 1.0f / (1.0f + expf(-mean * (1.0f/KSPT)));
        float su = 0.0f;
        for (int s = 0; s < KSPT; s++) { float e2 = expf(at[tid*KSPT + s] - m); at[tid*KSPT + s] = e2; su += e2; }
        float inv = 1.0f / su;
        for (int s = 0; s < KSPT; s++) at[tid*KSPT + s] *= inv;
    }
    __syncthreads();
    for (int e = tid; e < NT*HD; e += 256) {
        int t = e >> 5, d = e & 31;
        float sum = 0.0f;
        #pragma unroll
        for (int s = 0; s < KSPT; s++) sum += at[t*KSPT + s] * vh[s*HD + d];
        g_obuf_bf[((size_t)widx*NT + t)*CC + nh*HD + d] = __float2bfloat16(sum * gate[t]);
    }
}

// ---------------- launch ----------------
extern "C" void kernel_launch(void* const* d_in, const int* in_sizes, int n_in,
                              void* d_out, int out_size) {
    const float* x       = (const float*)d_in[0];
    const float* norm1_g = (const float*)d_in[1];
    const float* norm1_b = (const float*)d_in[2];
    const float* wq      = (const float*)d_in[3];
    const float* bq      = (const float*)d_in[4];
    const float* wk      = (const float*)d_in[5];
    const float* bk      = (const float*)d_in[6];
    const float* wv      = (const float*)d_in[7];
    const float* bv      = (const float*)d_in[8];
    const float* wproj   = (const float*)d_in[9];
    const float* bproj   = (const float*)d_in[10];
    const float* wch     = (const float*)d_in[11];
    const float* bch     = (const float*)d_in[12];
    const float* rpb     = (const float*)d_in[13];
    const float* norm2_g = (const float*)d_in[14];
    const float* norm2_b = (const float*)d_in[15];
    const float* w1      = (const float*)d_in[16];
    const float* b1      = (const float*)d_in[17];
    const float* w2      = (const float*)d_in[18];
    const float* b2      = (const float*)d_in[19];
    float* out = (float*)d_out;

    __nv_bfloat16 *p_xw_bf, *p_qcha1_bf, *p_k_bf, *p_vbuf_bf, *p_vproj_bf, *p_obuf_bf, *p_xn2_bf, *p_h_bf;
    __nv_bfloat16 *p_wq_t, *p_wk_t, *p_wv_t, *p_wproj_t, *p_w1_t, *p_w2_t;
    float *p_q;
    cudaGetSymbolAddress((void**)&p_xw_bf, g_xw_bf);
    cudaGetSymbolAddress((void**)&p_q, g_q);
    cudaGetSymbolAddress((void**)&p_qcha1_bf, g_qcha1_bf);
    cudaGetSymbolAddress((void**)&p_k_bf, g_k_bf);
    cudaGetSymbolAddress((void**)&p_vbuf_bf, g_vbuf_bf);
    cudaGetSymbolAddress((void**)&p_vproj_bf, g_vproj_bf);
    cudaGetSymbolAddress((void**)&p_obuf_bf, g_obuf_bf);
    cudaGetSymbolAddress((void**)&p_xn2_bf, g_xn2_bf);
    cudaGetSymbolAddress((void**)&p_h_bf, g_h_bf);
    cudaGetSymbolAddress((void**)&p_wq_t, g_wq_t);
    cudaGetSymbolAddress((void**)&p_wk_t, g_wk_t);
    cudaGetSymbolAddress((void**)&p_wv_t, g_wv_t);
    cudaGetSymbolAddress((void**)&p_wproj_t, g_wproj_t);
    cudaGetSymbolAddress((void**)&p_w1_t, g_w1_t);
    cudaGetSymbolAddress((void**)&p_w2_t, g_w2_t);

    cudaFuncSetAttribute(gemm_bf16_kernel<0,1,0,0>, cudaFuncAttributeMaxDynamicSharedMemorySize, GEMM_SMEM);
    cudaFuncSetAttribute(gemm_bf16_kernel<0,0,1,0>, cudaFuncAttributeMaxDynamicSharedMemorySize, GEMM_SMEM);
    cudaFuncSetAttribute(gemm_bf16_kernel<0,1,0,1>, cudaFuncAttributeMaxDynamicSharedMemorySize, GEMM_SMEM);
    cudaFuncSetAttribute(gemm_bf16_kernel<1,0,1,0>, cudaFuncAttributeMaxDynamicSharedMemorySize, GEMM_SMEM);

    // 0) all weight transposes in one launch
    wtrans_all_kernel<<<720, dim3(32, 8)>>>(wq, p_wq_t, wk, p_wk_t, wv, p_wv_t,
                                            wproj, p_wproj_t, w1, p_w1_t, w2, p_w2_t);
    // 1) LN1 + window partition -> g_xw_bf
    ln1_window_kernel<<<ROWS, 256>>>(x, norm1_g, norm1_b);
    // 2) q = xw @ wq + bq -> g_q (fp32)
    gemm_bf16_kernel<0,1,0,0><<<dim3(CC/128, ROWS/128), 256, GEMM_SMEM>>>(
        p_xw_bf, p_wq_t, bq, nullptr, p_q, nullptr, ROWS, CC, CC);
    // 3) top-k + gathers
    topk_stats_kernel<<<BN, 256>>>(wch, bch);
    // 4) k = qcha1 @ wk + bk -> g_k_bf
    gemm_bf16_kernel<0,0,1,0><<<dim3((CC/2)/128, ROWS/128), 256, GEMM_SMEM>>>(
        p_qcha1_bf, p_wk_t, bk, nullptr, nullptr, p_k_bf, ROWS, CC/2, CC/2);
    // 5) v = vbuf @ wv + bv -> g_vproj_bf   (ncu capture lands here)
    gemm_bf16_kernel<0,0,1,0><<<dim3(CC/128, MV/128), 256, GEMM_SMEM>>>(
        p_vbuf_bf, p_wv_t, bv, nullptr, nullptr, p_vproj_bf, MV, CC, CC);
    // 6) attention -> g_obuf_bf
    attn_kernel<<<BN, 256>>>(rpb);
    // 7) proj + window reverse + residual -> d_out (fused)
    gemm_bf16_kernel<0,1,0,1><<<dim3(CC/128, ROWS/128), 256, GEMM_SMEM>>>(
        p_obuf_bf, p_wproj_t, bproj, x, out, nullptr, ROWS, CC, CC);
    // 8) LN2(d_out) -> g_xn2_bf
    ln2_kernel<<<ROWS, 256>>>(out, norm2_g, norm2_b);
    // 9) h = gelu(xn2 @ w1 + b1) -> g_h_bf (bf16 only)
    gemm_bf16_kernel<1,0,1,0><<<dim3(MLPH/128, ROWS/128), 256, GEMM_SMEM>>>(
        p_xn2_bf, p_w1_t, b1, nullptr, nullptr, p_h_bf, ROWS, CC, MLPH);
    // 10) out = out + h @ w2 + b2
    gemm_bf16_kernel<0,1,0,0><<<dim3(CC/128, ROWS/128), 256, GEMM_SMEM>>>(
        p_h_bf, p_w2_t, b2, out, out, nullptr, ROWS, MLPH, CC);
}

// round 7
// speedup vs baseline: 5.1954x; 1.1704x over previous
#include <cuda_runtime.h>
#include <cuda_bf16.h>
#include <math.h>
#include <stdint.h>

// ---------------- problem constants ----------------
#define BB   32
#define HH   56
#define WW   56
#define CC   256
#define WS   7
#define NH   8
#define HD   32
#define KCH  16
#define KSPT 28
#define NT   49          // tokens per window
#define MLPH 1024
#define LL   (HH*WW)     // 3136
#define ROWS (BB*LL)     // 100352
#define BW   2048        // windows
#define BN   (BW*NH)     // 16384
#define MV   (BW*KSPT)   // 57344 (v rows)
#define SCALE_F 0.17677669529663687f   // 32^-0.5

// ---------------- static scratch (no allocations allowed) ----------------
__device__ __nv_bfloat16 g_xw_bf[ROWS*CC];        // LN1 windowed (bf16) -> q gemm A
__device__ float         g_q[ROWS*CC];            // q fp32 (topk reads)
__device__ __nv_bfloat16 g_qcha1_bf[BW*NT*(CC/2)];// channel-gathered q (bf16) -> k gemm A, attn
__device__ __nv_bfloat16 g_k_bf[ROWS*(CC/2)];     // k bf16 (attn reads)
__device__ __nv_bfloat16 g_vbuf_bf[MV*CC];        // gathered v input (bf16) -> v gemm A
__device__ __nv_bfloat16 g_vproj_bf[MV*CC];       // v projected bf16 (attn reads)
__device__ __nv_bfloat16 g_obuf_bf[ROWS*CC];      // attn out (bf16) -> proj gemm A
__device__ __nv_bfloat16 g_xn2_bf[ROWS*CC];       // LN2 out (bf16) -> mlp1 A
__device__ __nv_bfloat16 g_h_bf[(size_t)ROWS*MLPH]; // mlp hidden (bf16)
__device__ int           g_sidx[BN*KSPT];
// transposed bf16 weights (N-major, K contiguous)
__device__ __nv_bfloat16 g_wq_t[CC*CC];
__device__ __nv_bfloat16 g_wk_t[(CC/2)*(CC/2)];
__device__ __nv_bfloat16 g_wv_t[CC*CC];
__device__ __nv_bfloat16 g_wproj_t[CC*CC];
__device__ __nv_bfloat16 g_w1_t[CC*MLPH];
__device__ __nv_bfloat16 g_w2_t[MLPH*CC];

// ---------------- small helpers ----------------
__device__ __forceinline__ float gelu_exact(float x) {
    return 0.5f * x * (1.0f + erff(x * 0.70710678118654752f));
}

__device__ __forceinline__ float blockReduceSum256(float val) {
    __shared__ float sh[8];
    int lane = threadIdx.x & 31, wid = threadIdx.x >> 5;
    #pragma unroll
    for (int o = 16; o > 0; o >>= 1) val += __shfl_xor_sync(0xffffffffu, val, o);
    if (lane == 0) sh[wid] = val;
    __syncthreads();
    float r;
    if (wid == 0) {
        float v = (lane < 8) ? sh[lane] : 0.0f;
        #pragma unroll
        for (int o = 4; o > 0; o >>= 1) v += __shfl_xor_sync(0xffffffffu, v, o);
        if (lane == 0) sh[0] = v;
    }
    __syncthreads();
    r = sh[0];
    __syncthreads();
    return r;
}

__device__ __forceinline__ uint32_t smem_u32(const void* p) {
    return (uint32_t)__cvta_generic_to_shared(p);
}
__device__ __forceinline__ void cp_async16(uint32_t smem_dst, const void* gmem_src) {
    asm volatile("cp.async.ca.shared.global [%0], [%1], 16;\n" :: "r"(smem_dst), "l"(gmem_src));
}
#define CP_COMMIT()  asm volatile("cp.async.commit_group;\n" ::: "memory")
#define CP_WAIT(n)   asm volatile("cp.async.wait_group %0;\n" :: "n"(n) : "memory")

__device__ __forceinline__ void mma_bf16(float c[4], const uint32_t a[4], const uint32_t b[2]) {
    asm volatile(
        "mma.sync.aligned.m16n8k16.row.col.f32.bf16.bf16.f32 "
        "{%0,%1,%2,%3},{%4,%5,%6,%7},{%8,%9},{%0,%1,%2,%3};"
        : "+f"(c[0]), "+f"(c[1]), "+f"(c[2]), "+f"(c[3])
        : "r"(a[0]), "r"(a[1]), "r"(a[2]), "r"(a[3]), "r"(b[0]), "r"(b[1]));
}

// window-layout row -> (B, H*W) row
__device__ __forceinline__ int winrev_row(int wr) {
    int widx = wr / NT, token = wr % NT;
    int b = widx >> 6, rem = widx & 63;
    int wh = rem >> 3, ww = rem & 7;
    int h = wh * WS + token / WS;
    int w = ww * WS + token % WS;
    return b * LL + h * WW + w;
}

// ---------------- fused weight transpose+convert (all 6 weights, 1 launch) ----------------
__global__ void wtrans_all_kernel(
    const float* __restrict__ wq, __nv_bfloat16* __restrict__ wqt,
    const float* __restrict__ wk, __nv_bfloat16* __restrict__ wkt,
    const float* __restrict__ wv, __nv_bfloat16* __restrict__ wvt,
    const float* __restrict__ wp, __nv_bfloat16* __restrict__ wpt,
    const float* __restrict__ w1, __nv_bfloat16* __restrict__ w1t,
    const float* __restrict__ w2, __nv_bfloat16* __restrict__ w2t) {
    __shared__ float t[32][33];
    int bid = blockIdx.x;
    const float* W; __nv_bfloat16* Wt; int K, N, local;
    if      (bid < 64)  { W = wq; Wt = wqt; K = 256;  N = 256;  local = bid; }
    else if (bid < 80)  { W = wk; Wt = wkt; K = 128;  N = 128;  local = bid - 64; }
    else if (bid < 144) { W = wv; Wt = wvt; K = 256;  N = 256;  local = bid - 80; }
    else if (bid < 208) { W = wp; Wt = wpt; K = 256;  N = 256;  local = bid - 144; }
    else if (bid < 464) { W = w1; Wt = w1t; K = 256;  N = 1024; local = bid - 208; }
    else                { W = w2; Wt = w2t; K = 1024; N = 256;  local = bid - 464; }
    int tpx = N >> 5;
    int txi = local % tpx, tyi = local / tpx;
    int k0 = tyi * 32, n0 = txi * 32;
    int tx = threadIdx.x, ty = threadIdx.y;   // 32 x 8
    for (int i = ty; i < 32; i += 8) t[i][tx] = W[(size_t)(k0 + i) * N + n0 + tx];
    __syncthreads();
    for (int i = ty; i < 32; i += 8)
        Wt[(size_t)(n0 + i) * K + k0 + tx] = __float2bfloat16(t[tx][i]);
}

// ---------------- bf16 HMMA GEMM: D = act(A@W + bias) [+res], optional winrev remap ----------------
#define TSTR 72
#define TBUF (128*TSTR)
#define GEMM_SMEM (4*TBUF*2)   // 73728 bytes

template<int ACT, int OUTF32, int OUTBF, int WREV>
__global__ void __launch_bounds__(256, 2)
gemm_bf16_kernel(const __nv_bfloat16* __restrict__ A, const __nv_bfloat16* __restrict__ Bt,
                 const float* __restrict__ bias, const float* __restrict__ res,
                 float* __restrict__ D, __nv_bfloat16* __restrict__ Dbf,
                 int M, int Kt, int Ncols) {
    extern __shared__ __nv_bfloat16 sm[];
    __nv_bfloat16* As[2] = { sm, sm + TBUF };
    __nv_bfloat16* Bs[2] = { sm + 2*TBUF, sm + 3*TBUF };

    int tid = threadIdx.x;
    int warp = tid >> 5, lane = tid & 31;
    int g = lane >> 2, tig = lane & 3;
    int wm = warp >> 2, wn = warp & 3;   // 2 x 4 warp grid
    int bm = blockIdx.y * 128, bn = blockIdx.x * 128;

    float acc[4][4][4];
    #pragma unroll
    for (int mi = 0; mi < 4; mi++)
        #pragma unroll
        for (int ni = 0; ni < 4; ni++)
            #pragma unroll
            for (int j = 0; j < 4; j++) acc[mi][ni][j] = 0.0f;

    int T = Kt >> 6;

    auto issue = [&](int t, int buf) {
        int k0 = t << 6;
        #pragma unroll
        for (int i = 0; i < 4; i++) {
            int idx = tid + i * 256;
            int r = idx >> 3, q = idx & 7;
            cp_async16(smem_u32(&As[buf][r * TSTR + q * 8]),
                       A + (size_t)(bm + r) * Kt + k0 + q * 8);
        }
        #pragma unroll
        for (int i = 0; i < 4; i++) {
            int idx = tid + i * 256;
            int r = idx >> 3, q = idx & 7;
            cp_async16(smem_u32(&Bs[buf][r * TSTR + q * 8]),
                       Bt + (size_t)(bn + r) * Kt + k0 + q * 8);
        }
        CP_COMMIT();
    };

    issue(0, 0);

    for (int t = 0; t < T; t++) {
        int buf = t & 1;
        if (t + 1 < T) {
            issue(t + 1, buf ^ 1);
            CP_WAIT(1);
        } else {
            CP_WAIT(0);
        }
        __syncthreads();

        const __nv_bfloat16* as = As[buf];
        const __nv_bfloat16* bs = Bs[buf];

        #pragma unroll
        for (int kk = 0; kk < 64; kk += 16) {
            uint32_t af[4][4], bfr[4][2];
            #pragma unroll
            for (int mi = 0; mi < 4; mi++) {
                int r = wm*64 + mi*16 + g;
                af[mi][0] = *reinterpret_cast<const uint32_t*>(&as[(r    )*TSTR + kk +     2*tig]);
                af[mi][1] = *reinterpret_cast<const uint32_t*>(&as[(r + 8)*TSTR + kk +     2*tig]);
                af[mi][2] = *reinterpret_cast<const uint32_t*>(&as[(r    )*TSTR + kk + 8 + 2*tig]);
                af[mi][3] = *reinterpret_cast<const uint32_t*>(&as[(r + 8)*TSTR + kk + 8 + 2*tig]);
            }
            #pragma unroll
            for (int ni = 0; ni < 4; ni++) {
                int c = wn*32 + ni*8 + g;
                bfr[ni][0] = *reinterpret_cast<const uint32_t*>(&bs[c*TSTR + kk +     2*tig]);
                bfr[ni][1] = *reinterpret_cast<const uint32_t*>(&bs[c*TSTR + kk + 8 + 2*tig]);
            }
            #pragma unroll
            for (int mi = 0; mi < 4; mi++)
                #pragma unroll
                for (int ni = 0; ni < 4; ni++)
                    mma_bf16(acc[mi][ni], af[mi], bfr[ni]);
        }
        __syncthreads();
    }

    #pragma unroll
    for (int mi = 0; mi < 4; mi++) {
        int r0 = bm + wm*64 + mi*16 + g;
        int r1 = r0 + 8;
        int o0 = WREV ? winrev_row(r0) : r0;
        int o1 = WREV ? winrev_row(r1) : r1;
        #pragma unroll
        for (int ni = 0; ni < 4; ni++) {
            int col = bn + wn*32 + ni*8 + tig*2;
            const float2 bi = *reinterpret_cast<const float2*>(bias + col);
            float v0 = acc[mi][ni][0] + bi.x;
            float v1 = acc[mi][ni][1] + bi.y;
            float v2 = acc[mi][ni][2] + bi.x;
            float v3 = acc[mi][ni][3] + bi.y;
            if (ACT == 1) { v0 = gelu_exact(v0); v1 = gelu_exact(v1); v2 = gelu_exact(v2); v3 = gelu_exact(v3); }
            size_t i0 = (size_t)o0 * Ncols + col;
            size_t i1 = (size_t)o1 * Ncols + col;
            if (res) {
                const float2 ra = *reinterpret_cast<const float2*>(res + i0);
                const float2 rb = *reinterpret_cast<const float2*>(res + i1);
                v0 += ra.x; v1 += ra.y; v2 += rb.x; v3 += rb.y;
            }
            if (OUTF32) {
                *reinterpret_cast<float2*>(D + i0) = make_float2(v0, v1);
                *reinterpret_cast<float2*>(D + i1) = make_float2(v2, v3);
            }
            if (OUTBF) {
                __nv_bfloat162 p0 = __floats2bfloat162_rn(v0, v1);
                __nv_bfloat162 p1 = __floats2bfloat162_rn(v2, v3);
                *reinterpret_cast<__nv_bfloat162*>(Dbf + i0) = p0;
                *reinterpret_cast<__nv_bfloat162*>(Dbf + i1) = p1;
            }
        }
    }
}

// ---------------- LN1 + window partition (bf16 out) ----------------
__global__ void ln1_window_kernel(const float* __restrict__ x,
                                  const float* __restrict__ g,
                                  const float* __restrict__ b) {
    int row = blockIdx.x, tid = threadIdx.x;
    float v = x[(size_t)row*CC + tid];
    float s1 = blockReduceSum256(v);
    float s2 = blockReduceSum256(v*v);
    float mu = s1 * (1.0f/CC);
    float var = s2 * (1.0f/CC) - mu*mu;
    float rstd = rsqrtf(var + 1e-5f);
    float o = (v - mu) * rstd * g[tid] + b[tid];
    int bidx = row / LL, l = row % LL;
    int h = l / WW, w = l % WW;
    int widx = (bidx*8 + h/WS)*8 + (w/WS);
    int token = (h%WS)*WS + (w%WS);
    g_xw_bf[((size_t)widx*NT + token)*CC + tid] = __float2bfloat16(o);
}

// ---------------- LN2 (bf16 out) ----------------
__global__ void ln2_kernel(const float* __restrict__ x,
                           const float* __restrict__ g,
                           const float* __restrict__ b) {
    int row = blockIdx.x, tid = threadIdx.x;
    float v = x[(size_t)row*CC + tid];
    float s1 = blockReduceSum256(v);
    float s2 = blockReduceSum256(v*v);
    float mu = s1 * (1.0f/CC);
    float var = s2 * (1.0f/CC) - mu*mu;
    float rstd = rsqrtf(var + 1e-5f);
    g_xn2_bf[(size_t)row*CC + tid] = __float2bfloat16((v - mu) * rstd * g[tid] + b[tid]);
}

// ---------------- warp-per-(window,head) top-k + gathers ----------------
// block = 256 (8 warps = 8 units), grid = BN/8. No block-level syncs.
#define TKQT  (NT*33)            // padded q tile floats per warp
#define TKREG (TKQT + 49 + 28 + 2)   // + tmean + sidx(int) + pad
#define TOPK_SMEM (8*TKREG*4)

__global__ void __launch_bounds__(256)
topk_warp_kernel(const float* __restrict__ wch, const float* __restrict__ bch) {
    extern __shared__ float tsm[];
    int wid = threadIdx.x >> 5, lane = threadIdx.x & 31;
    float* qt  = tsm + wid * TKREG;
    float* tm  = qt + TKQT;
    int*   sidx = (int*)(tm + 49);
    int bn = blockIdx.x * 8 + wid;
    int widx = bn >> 3, nh = bn & 7;

    // load q column (channel = lane) + running mean/max
    const float* base = g_q + (size_t)widx*NT*CC + nh*HD + lane;
    float cs = 0.0f, cm = -1e30f;
    #pragma unroll
    for (int t = 0; t < NT; t++) {
        float v = base[(size_t)t*CC];
        qt[t*33 + lane] = v;
        cs += v; cm = fmaxf(cm, v);
    }
    float cmean = cs * (1.0f/NT);
    __syncwarp();

    // token means (t = lane, lane+32)
    for (int t = lane; t < NT; t += 32) {
        float s = 0.0f;
        #pragma unroll
        for (int hd = 0; hd < HD; hd++) s += qt[t*33 + hd];
        tm[t] = s * (1.0f/HD);
    }
    __syncwarp();

    // channel score (channel = lane)
    float sc = bch[lane];
    #pragma unroll
    for (int i = 0; i < HD; i++) {
        float cmi = __shfl_sync(0xffffffffu, cmean, i);
        float cxi = __shfl_sync(0xffffffffu, cm, i);
        sc += cmi * wch[i*HD + lane] + cxi * wch[(HD+i)*HD + lane];
    }
    sc = gelu_exact(sc);   // softmax before top_k is monotonic -> skip

    // channel top-16 by stable rank counting
    int cnt = 0;
    #pragma unroll
    for (int j = 0; j < HD; j++) {
        float sj = __shfl_sync(0xffffffffu, sc, j);
        cnt += (sj > sc) || (sj == sc && j < lane);
    }
    int cflag = cnt < KCH;
    unsigned cmask = __ballot_sync(0xffffffffu, cflag);
    int cpos = __popc(cmask & ((1u << lane) - 1u));

    // spatial top-28 by stable rank counting (t = lane, lane+32)
    float t0v = tm[lane];
    float t1v = (lane + 32 < NT) ? tm[lane + 32] : -1e30f;
    int scnt0 = 0, scnt1 = 0;
    #pragma unroll
    for (int j = 0; j < NT; j++) {
        float tj = tm[j];
        scnt0 += (tj > t0v) || (tj == t0v && j < lane);
        scnt1 += (tj > t1v) || (tj == t1v && j < lane + 32);
    }
    int sflag0 = scnt0 < KSPT;
    int sflag1 = (lane + 32 < NT) && (scnt1 < KSPT);
    unsigned m0 = __ballot_sync(0xffffffffu, sflag0);
    unsigned m1 = __ballot_sync(0xffffffffu, sflag1);
    if (sflag0) sidx[__popc(m0 & ((1u << lane) - 1u))] = lane;
    if (sflag1) sidx[__popc(m0) + __popc(m1 & ((1u << lane) - 1u))] = lane + 32;
    __syncwarp();

    // qcha1 gather (selected channels write their column at sorted position)
    if (cflag) {
        __nv_bfloat16* dst = g_qcha1_bf + (size_t)widx*NT*(CC/2) + nh*KCH + cpos;
        #pragma unroll
        for (int t = 0; t < NT; t++)
            dst[(size_t)t*(CC/2)] = __float2bfloat16(qt[t*33 + lane]);
    }
    // vbuf gather (all channels, selected tokens)
    {
        __nv_bfloat16* dst = g_vbuf_bf + (size_t)widx*KSPT*CC + nh*HD + lane;
        #pragma unroll
        for (int s = 0; s < KSPT; s++) {
            int t = sidx[s];
            dst[(size_t)s*CC] = __float2bfloat16(qt[t*33 + lane]);
        }
    }
    if (lane < KSPT) g_sidx[bn*KSPT + lane] = sidx[lane];
}

// ---------------- warp-per-(window,head) attention ----------------
// block = 256 (8 warps), grid = BN/8. qa + v-column in registers, kh in smem.
__global__ void __launch_bounds__(256)
attn_warp_kernel(const float* __restrict__ rpb) {
    __shared__ float khs[8][NT*KCH];   // 8 x 784 floats = 25KB
    int wid = threadIdx.x >> 5, lane = threadIdx.x & 31;
    int bn = blockIdx.x * 8 + wid;
    int widx = bn >> 3, nh = bn & 7;
    float* kh = khs[wid];

    // load k rows (t = lane, lane+32), 16 bf16 each
    for (int t = lane; t < NT; t += 32) {
        const __nv_bfloat16* src = g_k_bf + ((size_t)widx*NT + t)*(CC/2) + nh*KCH;
        uint4 a = *reinterpret_cast<const uint4*>(src);
        uint4 b = *reinterpret_cast<const uint4*>(src + 8);
        const __nv_bfloat16* pa = reinterpret_cast<const __nv_bfloat16*>(&a);
        const __nv_bfloat16* pb = reinterpret_cast<const __nv_bfloat16*>(&b);
        #pragma unroll
        for (int j = 0; j < 8; j++) kh[t*KCH + j]     = __bfloat162float(pa[j]);
        #pragma unroll
        for (int j = 0; j < 8; j++) kh[t*KCH + 8 + j] = __bfloat162float(pb[j]);
    }

    // v column: lane = d, vreg[s] = v[s][d]
    float vreg[KSPT];
    #pragma unroll
    for (int s = 0; s < KSPT; s++)
        vreg[s] = __bfloat162float(g_vproj_bf[((size_t)widx*KSPT + s)*CC + nh*HD + lane]);

    // qa row: lane = s (<28), 16 channels in registers, pre-scaled
    float qa[KCH];
    int r2 = 0, c2 = 0;
    if (lane < KSPT) {
        int t2 = g_sidx[bn*KSPT + lane];
        r2 = t2 / WS; c2 = t2 % WS;
        const __nv_bfloat16* src = g_qcha1_bf + ((size_t)widx*NT + t2)*(CC/2) + nh*KCH;
        uint4 a = *reinterpret_cast<const uint4*>(src);
        uint4 b = *reinterpret_cast<const uint4*>(src + 8);
        const __nv_bfloat16* pa = reinterpret_cast<const __nv_bfloat16*>(&a);
        const __nv_bfloat16* pb = reinterpret_cast<const __nv_bfloat16*>(&b);
        #pragma unroll
        for (int j = 0; j < 8; j++) qa[j]     = __bfloat162float(pa[j]) * SCALE_F;
        #pragma unroll
        for (int j = 0; j < 8; j++) qa[8 + j] = __bfloat162float(pb[j]) * SCALE_F;
    } else {
        #pragma unroll
        for (int j = 0; j < KCH; j++) qa[j] = 0.0f;
    }
    __syncwarp();

    __nv_bfloat16* obase = g_obuf_bf + (size_t)widx*NT*CC + nh*HD + lane;
    const float inv_kspt = 1.0f / KSPT;
    for (int t = 0; t < NT; t++) {
        float sum = 0.0f;
        #pragma unroll
        for (int j = 0; j < KCH; j++) sum += kh[t*KCH + j] * qa[j];
        int rt = t / WS, ct = t % WS;
        int rel = (rt - r2 + WS - 1) * (2*WS - 1) + (ct - c2 + WS - 1);
        float at = sum + rpb[rel*NH + nh];
        if (lane >= KSPT) at = -1e30f;
        // row reductions over lanes (pads: -inf for max, 0 for sums)
        float m = at;
        #pragma unroll
        for (int o = 16; o > 0; o >>= 1) m = fmaxf(m, __shfl_xor_sync(0xffffffffu, m, o));
        float araw = (lane < KSPT) ? at : 0.0f;
        #pragma unroll
        for (int o = 16; o > 0; o >>= 1) araw += __shfl_xor_sync(0xffffffffu, araw, o);
        float gate = 1.0f / (1.0f + expf(-araw * inv_kspt));
        float e = expf(at - m);    // lanes >= 28 -> 0
        float es = e;
        #pragma unroll
        for (int o = 16; o > 0; o >>= 1) es += __shfl_xor_sync(0xffffffffu, es, o);
        float p = e * (gate / es);
        // o[t][d=lane] = sum_s p[s] * v[s][d]
        float acc = 0.0f;
        #pragma unroll
        for (int s = 0; s < KSPT; s++)
            acc += __shfl_sync(0xffffffffu, p, s) * vreg[s];
        obase[(size_t)t*CC] = __float2bfloat16(acc);
    }
}

// ---------------- launch ----------------
extern "C" void kernel_launch(void* const* d_in, const int* in_sizes, int n_in,
                              void* d_out, int out_size) {
    const float* x       = (const float*)d_in[0];
    const float* norm1_g = (const float*)d_in[1];
    const float* norm1_b = (const float*)d_in[2];
    const float* wq      = (const float*)d_in[3];
    const float* bq      = (const float*)d_in[4];
    const float* wk      = (const float*)d_in[5];
    const float* bk      = (const float*)d_in[6];
    const float* wv      = (const float*)d_in[7];
    const float* bv      = (const float*)d_in[8];
    const float* wproj   = (const float*)d_in[9];
    const float* bproj   = (const float*)d_in[10];
    const float* wch     = (const float*)d_in[11];
    const float* bch     = (const float*)d_in[12];
    const float* rpb     = (const float*)d_in[13];
    const float* norm2_g = (const float*)d_in[14];
    const float* norm2_b = (const float*)d_in[15];
    const float* w1      = (const float*)d_in[16];
    const float* b1      = (const float*)d_in[17];
    const float* w2      = (const float*)d_in[18];
    const float* b2      = (const float*)d_in[19];
    float* out = (float*)d_out;

    __nv_bfloat16 *p_xw_bf, *p_qcha1_bf, *p_k_bf, *p_vbuf_bf, *p_vproj_bf, *p_obuf_bf, *p_xn2_bf, *p_h_bf;
    __nv_bfloat16 *p_wq_t, *p_wk_t, *p_wv_t, *p_wproj_t, *p_w1_t, *p_w2_t;
    float *p_q;
    cudaGetSymbolAddress((void**)&p_xw_bf, g_xw_bf);
    cudaGetSymbolAddress((void**)&p_q, g_q);
    cudaGetSymbolAddress((void**)&p_qcha1_bf, g_qcha1_bf);
    cudaGetSymbolAddress((void**)&p_k_bf, g_k_bf);
    cudaGetSymbolAddress((void**)&p_vbuf_bf, g_vbuf_bf);
    cudaGetSymbolAddress((void**)&p_vproj_bf, g_vproj_bf);
    cudaGetSymbolAddress((void**)&p_obuf_bf, g_obuf_bf);
    cudaGetSymbolAddress((void**)&p_xn2_bf, g_xn2_bf);
    cudaGetSymbolAddress((void**)&p_h_bf, g_h_bf);
    cudaGetSymbolAddress((void**)&p_wq_t, g_wq_t);
    cudaGetSymbolAddress((void**)&p_wk_t, g_wk_t);
    cudaGetSymbolAddress((void**)&p_wv_t, g_wv_t);
    cudaGetSymbolAddress((void**)&p_wproj_t, g_wproj_t);
    cudaGetSymbolAddress((void**)&p_w1_t, g_w1_t);
    cudaGetSymbolAddress((void**)&p_w2_t, g_w2_t);

    cudaFuncSetAttribute(gemm_bf16_kernel<0,1,0,0>, cudaFuncAttributeMaxDynamicSharedMemorySize, GEMM_SMEM);
    cudaFuncSetAttribute(gemm_bf16_kernel<0,0,1,0>, cudaFuncAttributeMaxDynamicSharedMemorySize, GEMM_SMEM);
    cudaFuncSetAttribute(gemm_bf16_kernel<0,1,0,1>, cudaFuncAttributeMaxDynamicSharedMemorySize, GEMM_SMEM);
    cudaFuncSetAttribute(gemm_bf16_kernel<1,0,1,0>, cudaFuncAttributeMaxDynamicSharedMemorySize, GEMM_SMEM);
    cudaFuncSetAttribute(topk_warp_kernel, cudaFuncAttributeMaxDynamicSharedMemorySize, TOPK_SMEM);

    // 0) all weight transposes in one launch
    wtrans_all_kernel<<<720, dim3(32, 8)>>>(wq, p_wq_t, wk, p_wk_t, wv, p_wv_t,
                                            wproj, p_wproj_t, w1, p_w1_t, w2, p_w2_t);
    // 1) LN1 + window partition -> g_xw_bf
    ln1_window_kernel<<<ROWS, 256>>>(x, norm1_g, norm1_b);
    // 2) q = xw @ wq + bq -> g_q (fp32)
    gemm_bf16_kernel<0,1,0,0><<<dim3(CC/128, ROWS/128), 256, GEMM_SMEM>>>(
        p_xw_bf, p_wq_t, bq, nullptr, p_q, nullptr, ROWS, CC, CC);
    // 3) top-k + gathers (warp per unit)
    topk_warp_kernel<<<BN/8, 256, TOPK_SMEM>>>(wch, bch);
    // 4) k = qcha1 @ wk + bk -> g_k_bf
    gemm_bf16_kernel<0,0,1,0><<<dim3((CC/2)/128, ROWS/128), 256, GEMM_SMEM>>>(
        p_qcha1_bf, p_wk_t, bk, nullptr, nullptr, p_k_bf, ROWS, CC/2, CC/2);
    // 5) v = vbuf @ wv + bv -> g_vproj_bf
    gemm_bf16_kernel<0,0,1,0><<<dim3(CC/128, MV/128), 256, GEMM_SMEM>>>(
        p_vbuf_bf, p_wv_t, bv, nullptr, nullptr, p_vproj_bf, MV, CC, CC);
    // 6) attention (warp per unit) -> g_obuf_bf
    attn_warp_kernel<<<BN/8, 256>>>(rpb);
    // 7) proj + window reverse + residual -> d_out (fused)
    gemm_bf16_kernel<0,1,0,1><<<dim3(CC/128, ROWS/128), 256, GEMM_SMEM>>>(
        p_obuf_bf, p_wproj_t, bproj, x, out, nullptr, ROWS, CC, CC);
    // 8) LN2(d_out) -> g_xn2_bf
    ln2_kernel<<<ROWS, 256>>>(out, norm2_g, norm2_b);
    // 9) h = gelu(xn2 @ w1 + b1) -> g_h_bf (bf16 only)
    gemm_bf16_kernel<1,0,1,0><<<dim3(MLPH/128, ROWS/128), 256, GEMM_SMEM>>>(
        p_xn2_bf, p_w1_t, b1, nullptr, nullptr, p_h_bf, ROWS, CC, MLPH);
    // 10) out = out + h @ w2 + b2
    gemm_bf16_kernel<0,1,0,0><<<dim3(CC/128, ROWS/128), 256, GEMM_SMEM>>>(
        p_h_bf, p_w2_t, b2, out, out, nullptr, ROWS, MLPH, CC);
}